// round 5
// baseline (speedup 1.0000x reference)
#include <cuda_runtime.h>

#define NN   50000
#define NE   800000
#define NREL 6
#define NL   8
#define DD   256
#define NG   512

// ---------------- scratch (device globals; no allocation allowed) ----------------
__device__ float g_h   [(size_t)NN * DD];   // 51.2 MB
__device__ float g_hnew[(size_t)NN * DD];   // 51.2 MB
__device__ float g_t1  [(size_t)NN * DD];   // 51.2 MB
__device__ float g_pool[NG * DD];
__device__ float g_z1  [NG * 1024];
__device__ float g_z2  [NG * 512];

// ---------------- encoder: h = x @ enc_W + enc_b ----------------
__global__ void encoder_k(const float* __restrict__ x,
                          const float* __restrict__ W,
                          const float* __restrict__ b) {
    int n = blockIdx.x;
    __shared__ float xr[13];
    if (threadIdx.x < 13) xr[threadIdx.x] = x[n * 13 + threadIdx.x];
    __syncthreads();
    int d = threadIdx.x;
    float s = b[d];
#pragma unroll
    for (int k = 0; k < 13; k++) s += xr[k] * W[k * DD + d];
    g_h[(size_t)n * DD + d] = s;
}

// ---------------- generic fp32 SGEMM: C (+)= A[M,K] @ B[K,N] (+bias)(relu) ----------------
template <int BM, int BN, int BK, int TM, int TN>
__global__ __launch_bounds__((BM / TM) * (BN / TN))
void sgemm_k(const float* __restrict__ A, const float* __restrict__ B,
             float* __restrict__ C, int M, int N, int K,
             const float* __restrict__ bias, int relu, int accum) {
    constexpr int NT = (BM / TM) * (BN / TN);
    __shared__ float As[BK * BM];
    __shared__ float Bs[BK * BN];

    int tid = threadIdx.x;
    int bm0 = blockIdx.y * BM;
    int bn0 = blockIdx.x * BN;
    int tr  = tid / (BN / TN);
    int tc  = tid % (BN / TN);

    float acc[TM][TN];
#pragma unroll
    for (int i = 0; i < TM; i++)
#pragma unroll
        for (int j = 0; j < TN; j++) acc[i][j] = 0.f;

    constexpr int AIT = (BM * BK / 4) / NT;
    constexpr int BIT = (BK * BN / 4) / NT;

    for (int k0 = 0; k0 < K; k0 += BK) {
#pragma unroll
        for (int it = 0; it < AIT; it++) {
            int i  = tid + it * NT;
            int ar = i / (BK / 4);
            int ac = (i % (BK / 4)) * 4;
            float4 v = make_float4(0.f, 0.f, 0.f, 0.f);
            int grow = bm0 + ar;
            if (grow < M) v = *(const float4*)(A + (size_t)grow * K + k0 + ac);
            As[(ac + 0) * BM + ar] = v.x;
            As[(ac + 1) * BM + ar] = v.y;
            As[(ac + 2) * BM + ar] = v.z;
            As[(ac + 3) * BM + ar] = v.w;
        }
#pragma unroll
        for (int it = 0; it < BIT; it++) {
            int i  = tid + it * NT;
            int br = i / (BN / 4);
            int bc = (i % (BN / 4)) * 4;
            *(float4*)(Bs + br * BN + bc) =
                *(const float4*)(B + (size_t)(k0 + br) * N + bn0 + bc);
        }
        __syncthreads();
#pragma unroll
        for (int k = 0; k < BK; k++) {
            float ra[TM], rb[TN];
#pragma unroll
            for (int i = 0; i < TM; i++) ra[i] = As[k * BM + tr * TM + i];
#pragma unroll
            for (int j = 0; j < TN; j++) rb[j] = Bs[k * BN + tc * TN + j];
#pragma unroll
            for (int i = 0; i < TM; i++)
#pragma unroll
                for (int j = 0; j < TN; j++) acc[i][j] += ra[i] * rb[j];
        }
        __syncthreads();
    }

#pragma unroll
    for (int i = 0; i < TM; i++) {
        int row = bm0 + tr * TM + i;
        if (row >= M) continue;
#pragma unroll
        for (int j = 0; j < TN; j += 4) {
            int col = bn0 + tc * TN + j;
            float* cp = C + (size_t)row * N + col;
            float4 v = make_float4(acc[i][j], acc[i][j + 1], acc[i][j + 2], acc[i][j + 3]);
            if (bias) {
                float4 bb = *(const float4*)(bias + col);
                v.x += bb.x; v.y += bb.y; v.z += bb.z; v.w += bb.w;
            }
            if (accum) {
                float4 c0 = *(const float4*)cp;
                v.x += c0.x; v.y += c0.y; v.z += c0.z; v.w += c0.w;
            }
            if (relu) {
                v.x = fmaxf(v.x, 0.f); v.y = fmaxf(v.y, 0.f);
                v.z = fmaxf(v.z, 0.f); v.w = fmaxf(v.w, 0.f);
            }
            *(float4*)cp = v;
        }
    }
}

// ---------------- init h_new = h (skip) + conv_b ----------------
__global__ void init_hnew_k(const float* __restrict__ convb) {
    int idx = blockIdx.x * blockDim.x + threadIdx.x;
    if (idx >= NN * 64) return;
    int n = idx >> 6, c = idx & 63;
    float4 h = *(const float4*)(g_h + (size_t)n * DD + c * 4);
    float4 b = *(const float4*)(convb + c * 4);
    float4 o = make_float4(h.x + b.x, h.y + b.y, h.z + b.z, h.w + b.w);
    *(float4*)(g_hnew + (size_t)n * DD + c * 4) = o;
}

// ---------------- edge scatter (one relation): h_new[dst] += t1[src] ----------------
__global__ void edge_k(const int* __restrict__ ei,
                       const int* __restrict__ et, int rel) {
    int w = (blockIdx.x * blockDim.x + threadIdx.x) >> 5;
    if (w >= NE) return;
    if (et[w] != rel) return;
    int lane = threadIdx.x & 31;
    int src = ei[w];
    int dst = ei[NE + w];
    const float4* s = (const float4*)(g_t1 + (size_t)src * DD);
    float4 a = s[lane];
    float4 b = s[lane + 32];
    float* d = g_hnew + (size_t)dst * DD + lane * 4;
    atomicAdd(d + 0, a.x); atomicAdd(d + 1, a.y);
    atomicAdd(d + 2, a.z); atomicAdd(d + 3, a.w);
    atomicAdd(d + 128, b.x); atomicAdd(d + 129, b.y);
    atomicAdd(d + 130, b.z); atomicAdd(d + 131, b.w);
}

// ---------------- PReLU + row L2-normalize: h = normalize(prelu(h_new)) ----------------
__global__ void prelu_norm_k(const float* __restrict__ pa) {
    int n = blockIdx.x;
    int t = threadIdx.x;  // 64 threads
    float a = *pa;
    float4 v = *(const float4*)(g_hnew + (size_t)n * DD + t * 4);
    v.x = v.x > 0.f ? v.x : a * v.x;
    v.y = v.y > 0.f ? v.y : a * v.y;
    v.z = v.z > 0.f ? v.z : a * v.z;
    v.w = v.w > 0.f ? v.w : a * v.w;
    float s = v.x * v.x + v.y * v.y + v.z * v.z + v.w * v.w;
#pragma unroll
    for (int o = 16; o > 0; o >>= 1) s += __shfl_down_sync(0xffffffffu, s, o);
    __shared__ float sm[2];
    if ((t & 31) == 0) sm[t >> 5] = s;
    __syncthreads();
    float tot = sm[0] + sm[1];
    float inv = 1.f / fmaxf(sqrtf(tot), 1e-12f);
    v.x *= inv; v.y *= inv; v.z *= inv; v.w *= inv;
    *(float4*)(g_h + (size_t)n * DD + t * 4) = v;
}

// ---------------- zero ----------------
__global__ void zero_k(float* p, int n) {
    int i = blockIdx.x * blockDim.x + threadIdx.x;
    if (i < n) p[i] = 0.f;
}

// ---------------- global_add_pool: pooled[batch[n]] += g[n] ----------------
__global__ void pool_k(const int* __restrict__ batch) {
    int idx = blockIdx.x * blockDim.x + threadIdx.x;
    if (idx >= NN * 64) return;
    int n = idx >> 6, c = idx & 63;
    int bg = batch[n];
    float4 v = *(const float4*)(g_hnew + (size_t)n * DD + c * 4);
    float* d = g_pool + (size_t)bg * DD + c * 4;
    atomicAdd(d + 0, v.x); atomicAdd(d + 1, v.y);
    atomicAdd(d + 2, v.z); atomicAdd(d + 3, v.w);
}

// ---------------- final matvec: out = relu(z2 @ out_W + out_b) ----------------
__global__ void out_k(const float* __restrict__ W, const float* __restrict__ b,
                      float* __restrict__ out) {
    int g = blockIdx.x;
    int t = threadIdx.x;  // 128 threads
    float4 z = *(const float4*)(g_z2 + (size_t)g * 512 + t * 4);
    float4 w = *(const float4*)(W + t * 4);
    float s = z.x * w.x + z.y * w.y + z.z * w.z + z.w * w.w;
#pragma unroll
    for (int o = 16; o > 0; o >>= 1) s += __shfl_down_sync(0xffffffffu, s, o);
    __shared__ float sm[4];
    if ((t & 31) == 0) sm[t >> 5] = s;
    __syncthreads();
    if (t == 0) {
        float tot = sm[0] + sm[1] + sm[2] + sm[3] + b[0];
        out[g] = fmaxf(tot, 0.f);
    }
}

// ---------------- launch ----------------
extern "C" void kernel_launch(void* const* d_in, const int* in_sizes, int n_in,
                              void* d_out, int out_size) {
    const float* x      = (const float*)d_in[0];
    const int*   ei     = (const int*)d_in[1];    // int32 (JAX default x64-disabled)
    const int*   et     = (const int*)d_in[2];
    const int*   batch  = (const int*)d_in[3];
    const float* encW   = (const float*)d_in[4];
    const float* encb   = (const float*)d_in[5];
    const float* preluA = (const float*)d_in[6];
    const float* relW   = (const float*)d_in[7];
    const float* rootW  = (const float*)d_in[8];
    const float* convb  = (const float*)d_in[9];
    const float* gpW1   = (const float*)d_in[10];
    const float* gpb1   = (const float*)d_in[11];
    const float* gpW2   = (const float*)d_in[12];
    const float* gpb2   = (const float*)d_in[13];
    const float* fcW1   = (const float*)d_in[14];
    const float* fcb1   = (const float*)d_in[15];
    const float* fcW2   = (const float*)d_in[16];
    const float* fcb2   = (const float*)d_in[17];
    const float* outW   = (const float*)d_in[18];
    const float* outb   = (const float*)d_in[19];
    float*       out    = (float*)d_out;

    float *p_h, *p_hnew, *p_t1, *p_pool, *p_z1, *p_z2;
    cudaGetSymbolAddress((void**)&p_h, g_h);
    cudaGetSymbolAddress((void**)&p_hnew, g_hnew);
    cudaGetSymbolAddress((void**)&p_t1, g_t1);
    cudaGetSymbolAddress((void**)&p_pool, g_pool);
    cudaGetSymbolAddress((void**)&p_z1, g_z1);
    cudaGetSymbolAddress((void**)&p_z2, g_z2);

    dim3 gDD(DD / 128, (NN + 127) / 128);  // [50000,256] x [256,256] tiles

    // encoder
    encoder_k<<<NN, 256>>>(x, encW, encb);

    // 8 RGCN layers
    for (int l = 0; l < NL; l++) {
        // h_new = h (skip) + conv_b
        init_hnew_k<<<(NN * 64 + 255) / 256, 256>>>(convb + (size_t)l * DD);
        // h_new += h @ root_W[l]
        sgemm_k<128, 128, 16, 8, 8><<<gDD, 256>>>(
            p_h, rootW + (size_t)l * DD * DD, p_hnew, NN, DD, DD, nullptr, 0, 1);
        // per relation: t1 = h @ rel_W[l][r]; scatter edges of type r
        for (int r = 0; r < NREL; r++) {
            sgemm_k<128, 128, 16, 8, 8><<<gDD, 256>>>(
                p_h, relW + ((size_t)l * NREL + r) * DD * DD, p_t1,
                NN, DD, DD, nullptr, 0, 0);
            edge_k<<<(NE * 32) / 256, 256>>>(ei, et, r);
        }
        // h = normalize(prelu(h_new))
        prelu_norm_k<<<NN, 64>>>(preluA);
    }

    // graph head: g = relu(h@gpW1+b1)@gpW2+b2   (g stored in g_hnew)
    sgemm_k<128, 128, 16, 8, 8><<<gDD, 256>>>(p_h, gpW1, p_t1, NN, DD, DD, gpb1, 1, 0);
    sgemm_k<128, 128, 16, 8, 8><<<gDD, 256>>>(p_t1, gpW2, p_hnew, NN, DD, DD, gpb2, 0, 0);

    // pool
    zero_k<<<(NG * DD + 255) / 256, 256>>>(p_pool, NG * DD);
    pool_k<<<(NN * 64 + 255) / 256, 256>>>(batch);

    // MLP head
    sgemm_k<64, 64, 16, 4, 4><<<dim3(1024 / 64, NG / 64), 256>>>(
        p_pool, fcW1, p_z1, NG, 1024, DD, fcb1, 1, 0);
    sgemm_k<64, 64, 16, 4, 4><<<dim3(512 / 64, NG / 64), 256>>>(
        p_z1, fcW2, p_z2, NG, 512, 1024, fcb2, 1, 0);
    out_k<<<NG, 128>>>(outW, outb, out);
}

// round 8
// speedup vs baseline: 2.9196x; 2.9196x over previous
#include <cuda_runtime.h>
#include <cuda_bf16.h>
#include <cstdint>

#define NN   50000
#define NE   800000
#define NREL 6
#define NL   8
#define DD   256
#define NG   512
#define KK   768          // tripled K for bf16 split
#define NC   1792         // 7*256 (6 rel + root)
#define BM   128
#define BNT  128          // MMA N tile
#define BK   32
#define MT   391          // ceil(50000/128)
#define NTM  14           // 1792/128

// ---------------- scratch ----------------
__device__ float          g_h   [(size_t)NN * DD];
__device__ float          g_hnew[(size_t)NN * DD];
__device__ float          g_t1  [(size_t)NN * DD];
__device__ float          g_xW  [(size_t)NN * NC];      // 358 MB
__device__ __nv_bfloat16  g_Ahl [(size_t)NN * KK];      // 76.8 MB
__device__ __nv_bfloat16  g_Bt  [(size_t)NC * KK];      // 2.75 MB
__device__ int            g_deg [NN];
__device__ int            g_rowptr[NN + 1];
__device__ int            g_cursor[NN];
__device__ unsigned       g_epack[NE];
__device__ float          g_pool[NG * DD];
__device__ float          g_z1  [NG * 1024];
__device__ float          g_z2  [NG * 512];

// ---------------- PTX helpers (baseline ISA only: sm_80-class) ----------------
__device__ __forceinline__ uint32_t smem_u32(const void* p) {
    uint32_t a;
    asm("{ .reg .u64 t; cvta.to.shared.u64 t, %1; cvt.u32.u64 %0, t; }" : "=r"(a) : "l"(p));
    return a;
}
__device__ __forceinline__ void cp16(uint32_t s, const void* g) {
    asm volatile("cp.async.cg.shared.global [%0], [%1], 16;" :: "r"(s), "l"(g) : "memory");
}
__device__ __forceinline__ void cp_commit() {
    asm volatile("cp.async.commit_group;" ::: "memory");
}
template <int N>
__device__ __forceinline__ void cp_wait() {
    asm volatile("cp.async.wait_group %0;" :: "n"(N) : "memory");
}
__device__ __forceinline__ void ldsm4(uint32_t a, uint32_t* r) {
    asm volatile("ldmatrix.sync.aligned.m8n8.x4.shared.b16 {%0,%1,%2,%3}, [%4];"
                 : "=r"(r[0]), "=r"(r[1]), "=r"(r[2]), "=r"(r[3]) : "r"(a));
}
__device__ __forceinline__ void mma16816(float* c, const uint32_t* a, const uint32_t* b) {
    asm volatile(
        "mma.sync.aligned.m16n8k16.row.col.f32.bf16.bf16.f32 "
        "{%0,%1,%2,%3}, {%4,%5,%6,%7}, {%8,%9}, {%0,%1,%2,%3};"
        : "+f"(c[0]), "+f"(c[1]), "+f"(c[2]), "+f"(c[3])
        : "r"(a[0]), "r"(a[1]), "r"(a[2]), "r"(a[3]), "r"(b[0]), "r"(b[1]));
}
// swizzled byte offset within a [rows x 32 bf16] tile (64B rows, conflict-free ldmatrix)
__device__ __forceinline__ int SW(int row, int cb) {
    return row * 64 + (cb ^ (((row >> 1) & 3) << 4));
}

// ---------------- encoder ----------------
__global__ void encoder_k(const float* __restrict__ x, const float* __restrict__ W,
                          const float* __restrict__ b) {
    int n = blockIdx.x;
    __shared__ float xr[13];
    if (threadIdx.x < 13) xr[threadIdx.x] = x[n * 13 + threadIdx.x];
    __syncthreads();
    int d = threadIdx.x;
    float s = b[d];
#pragma unroll
    for (int k = 0; k < 13; k++) s += xr[k] * W[k * DD + d];
    g_h[(size_t)n * DD + d] = s;
}

// ---------------- CSR build ----------------
__global__ void zero_i_k(int* p, int n) {
    int i = blockIdx.x * blockDim.x + threadIdx.x;
    if (i < n) p[i] = 0;
}
__global__ void hist_k(const int* __restrict__ ei) {
    int e = blockIdx.x * blockDim.x + threadIdx.x;
    if (e < NE) atomicAdd(&g_deg[ei[NE + e]], 1);
}
__global__ void scan_k() {
    __shared__ int part[1024];
    int t = threadIdx.x;
    const int chunk = (NN + 1023) / 1024;
    int b = t * chunk, e = min(b + chunk, NN);
    int s = 0;
    for (int i = b; i < e; i++) s += g_deg[i];
    part[t] = s;
    __syncthreads();
    for (int off = 1; off < 1024; off <<= 1) {
        int v = (t >= off) ? part[t - off] : 0;
        __syncthreads();
        part[t] += v;
        __syncthreads();
    }
    int run = (t == 0) ? 0 : part[t - 1];
    for (int i = b; i < e; i++) {
        g_rowptr[i] = run;
        g_cursor[i] = run;
        run += g_deg[i];
    }
    if (t == 1023) g_rowptr[NN] = run;
}
__global__ void scatter_k(const int* __restrict__ ei, const int* __restrict__ et) {
    int e = blockIdx.x * blockDim.x + threadIdx.x;
    if (e >= NE) return;
    int dst = ei[NE + e];
    int pos = atomicAdd(&g_cursor[dst], 1);
    g_epack[pos] = (unsigned)ei[e] | ((unsigned)et[e] << 17);   // src:17 bits, type:3
}

// ---------------- bf16 split conversions ----------------
__global__ void convA_k() {
    int idx = blockIdx.x * blockDim.x + threadIdx.x;
    if (idx >= NN * DD) return;
    int n = idx >> 8, k = idx & 255;
    float v = g_h[idx];
    __nv_bfloat16 hi = __float2bfloat16(v);
    __nv_bfloat16 lo = __float2bfloat16(v - __bfloat162float(hi));
    __nv_bfloat16* a = g_Ahl + (size_t)n * KK;
    a[k] = hi; a[256 + k] = lo; a[512 + k] = hi;
}
__global__ void convB_k(const float* __restrict__ relW, const float* __restrict__ rootW, int l) {
    int idx = blockIdx.x * blockDim.x + threadIdx.x;
    if (idx >= NC * KK) return;
    int n = idx / KK, k = idx - n * KK;
    int kk = (k < 256) ? k : ((k < 512) ? k - 256 : k - 512);
    float w;
    if (n < 1536) {
        int r = n >> 8, c = n & 255;
        w = relW[((((size_t)l * NREL + r) * DD + kk) * DD) + c];
    } else {
        w = rootW[(((size_t)l * DD + kk) * DD) + (n - 1536)];
    }
    __nv_bfloat16 hi = __float2bfloat16(w);
    g_Bt[idx] = (k < 512) ? hi : __float2bfloat16(w - __bfloat162float(hi));
}

// ---------------- bf16 mma.sync GEMM: g_xW[M,1792] = Ahl[M,768] @ Bt^T ----------------
__global__ __launch_bounds__(256, 2) void mma_k(int M) {
    __shared__ __align__(16) unsigned char sA[2][BM * 64];    // 2 x 8 KB
    __shared__ __align__(16) unsigned char sB[2][BNT * 64];   // 2 x 8 KB

    int tid = threadIdx.x, lane = tid & 31, wid = tid >> 5;
    int wm = (wid & 3) * 32;          // warp m offset (4 warps down)
    int wn = (wid >> 2) * 64;         // warp n offset (2 warps across)
    int bm0 = blockIdx.y * BM, bn0 = blockIdx.x * BNT;

    uint32_t aA[2] = {smem_u32(sA[0]), smem_u32(sA[1])};
    uint32_t aB[2] = {smem_u32(sB[0]), smem_u32(sB[1])};

    float acc[2][8][4];
#pragma unroll
    for (int i = 0; i < 2; i++)
#pragma unroll
        for (int j = 0; j < 8; j++)
#pragma unroll
            for (int q = 0; q < 4; q++) acc[i][j][q] = 0.f;

    const __nv_bfloat16* A = g_Ahl;
    const __nv_bfloat16* B = g_Bt;

    // stage loader: 512 chunks of 16B each for A and B (2 per thread each)
    auto load_stage = [&](int buf, int kc) {
#pragma unroll
        for (int i = 0; i < 2; i++) {
            int id = tid + i * 256;
            int row = id >> 2, cb = (id & 3) * 16;
            int gr = min(bm0 + row, M - 1);
            cp16(aA[buf] + SW(row, cb), A + (size_t)gr * KK + kc * BK + cb / 2);
        }
#pragma unroll
        for (int i = 0; i < 2; i++) {
            int id = tid + i * 256;
            int row = id >> 2, cb = (id & 3) * 16;
            cp16(aB[buf] + SW(row, cb), B + (size_t)(bn0 + row) * KK + kc * BK + cb / 2);
        }
        cp_commit();
    };

    load_stage(0, 0);

    const int NKC = KK / BK;  // 24
    for (int kc = 0; kc < NKC; kc++) {
        int buf = kc & 1;
        if (kc + 1 < NKC) {
            load_stage(buf ^ 1, kc + 1);
            cp_wait<1>();
        } else {
            cp_wait<0>();
        }
        __syncthreads();

#pragma unroll
        for (int kk = 0; kk < 2; kk++) {            // two k16 steps per BK=32
            uint32_t areg[2][4];
#pragma unroll
            for (int mt = 0; mt < 2; mt++) {
                int row = wm + mt * 16 + (lane & 15);
                int cb = kk * 32 + ((lane >> 4) << 4);
                ldsm4(aA[buf] + SW(row, cb), areg[mt]);
            }
            uint32_t breg[8][2];
#pragma unroll
            for (int np = 0; np < 4; np++) {
                // non-trans ldmatrix: row-major [n][k] tile IS the col-major KxN B fragment
                int row = wn + np * 16 + ((lane >> 4) << 3) + (lane & 7);
                int cb = kk * 32 + (((lane >> 3) & 1) << 4);
                uint32_t r4[4];
                ldsm4(aB[buf] + SW(row, cb), r4);
                breg[np * 2 + 0][0] = r4[0]; breg[np * 2 + 0][1] = r4[1];
                breg[np * 2 + 1][0] = r4[2]; breg[np * 2 + 1][1] = r4[3];
            }
#pragma unroll
            for (int mt = 0; mt < 2; mt++)
#pragma unroll
                for (int nt = 0; nt < 8; nt++)
                    mma16816(acc[mt][nt], areg[mt], breg[nt]);
        }
        __syncthreads();
    }

    // epilogue: fp32 to g_xW
#pragma unroll
    for (int mt = 0; mt < 2; mt++) {
        int r0 = bm0 + wm + mt * 16 + (lane >> 2);
#pragma unroll
        for (int nt = 0; nt < 8; nt++) {
            int cn = bn0 + wn + nt * 8 + (lane & 3) * 2;
            if (r0 < M)
                *(float2*)(g_xW + (size_t)r0 * NC + cn) = make_float2(acc[mt][nt][0], acc[mt][nt][1]);
            if (r0 + 8 < M)
                *(float2*)(g_xW + (size_t)(r0 + 8) * NC + cn) = make_float2(acc[mt][nt][2], acc[mt][nt][3]);
        }
    }
}

// ---------------- fused gather + root + skip + bias + PReLU + L2 norm ----------------
__global__ void gather_k(const float* __restrict__ convb, const float* __restrict__ pa) {
    int row = blockIdx.x;
    int t = threadIdx.x;   // 64 threads, 4 cols each
    const float* xwr = g_xW + (size_t)row * NC;
    float4 acc = *(const float4*)(xwr + 1536 + t * 4);                 // root
    float4 h0  = *(const float4*)(g_h + (size_t)row * DD + t * 4);     // skip
    float4 cb  = *(const float4*)(convb + t * 4);
    acc.x += h0.x + cb.x; acc.y += h0.y + cb.y; acc.z += h0.z + cb.z; acc.w += h0.w + cb.w;
    int beg = g_rowptr[row], end = g_rowptr[row + 1];
    for (int i = beg; i < end; i++) {
        unsigned p = g_epack[i];
        int src = p & 0x1FFFF, typ = (p >> 17) & 7;
        float4 m = *(const float4*)(g_xW + (size_t)src * NC + typ * DD + t * 4);
        acc.x += m.x; acc.y += m.y; acc.z += m.z; acc.w += m.w;
    }
    float a = *pa;
    acc.x = acc.x > 0.f ? acc.x : a * acc.x;
    acc.y = acc.y > 0.f ? acc.y : a * acc.y;
    acc.z = acc.z > 0.f ? acc.z : a * acc.z;
    acc.w = acc.w > 0.f ? acc.w : a * acc.w;
    float s = acc.x * acc.x + acc.y * acc.y + acc.z * acc.z + acc.w * acc.w;
#pragma unroll
    for (int o = 16; o > 0; o >>= 1) s += __shfl_down_sync(0xffffffffu, s, o);
    __shared__ float sm[2];
    if ((t & 31) == 0) sm[t >> 5] = s;
    __syncthreads();
    float inv = 1.f / fmaxf(sqrtf(sm[0] + sm[1]), 1e-12f);
    acc.x *= inv; acc.y *= inv; acc.z *= inv; acc.w *= inv;
    *(float4*)(g_h + (size_t)row * DD + t * 4) = acc;
}

// ---------------- fp32 SGEMM (head) ----------------
template <int BM_, int BN_, int BK_, int TM_, int TN_>
__global__ __launch_bounds__((BM_ / TM_) * (BN_ / TN_))
void sgemm_k(const float* __restrict__ A, const float* __restrict__ B,
             float* __restrict__ C, int M, int N, int K,
             const float* __restrict__ bias, int relu) {
    constexpr int NT = (BM_ / TM_) * (BN_ / TN_);
    __shared__ float As[BK_ * BM_];
    __shared__ float Bs[BK_ * BN_];
    int tid = threadIdx.x;
    int bm0 = blockIdx.y * BM_, bn0 = blockIdx.x * BN_;
    int tr = tid / (BN_ / TN_), tc = tid % (BN_ / TN_);
    float acc[TM_][TN_];
#pragma unroll
    for (int i = 0; i < TM_; i++)
#pragma unroll
        for (int j = 0; j < TN_; j++) acc[i][j] = 0.f;
    constexpr int AIT = (BM_ * BK_ / 4) / NT;
    constexpr int BIT = (BK_ * BN_ / 4) / NT;
    for (int k0 = 0; k0 < K; k0 += BK_) {
#pragma unroll
        for (int it = 0; it < AIT; it++) {
            int i = tid + it * NT;
            int ar = i / (BK_ / 4), ac = (i % (BK_ / 4)) * 4;
            float4 v = make_float4(0.f, 0.f, 0.f, 0.f);
            int gr = bm0 + ar;
            if (gr < M) v = *(const float4*)(A + (size_t)gr * K + k0 + ac);
            As[(ac + 0) * BM_ + ar] = v.x; As[(ac + 1) * BM_ + ar] = v.y;
            As[(ac + 2) * BM_ + ar] = v.z; As[(ac + 3) * BM_ + ar] = v.w;
        }
#pragma unroll
        for (int it = 0; it < BIT; it++) {
            int i = tid + it * NT;
            int br = i / (BN_ / 4), bc = (i % (BN_ / 4)) * 4;
            *(float4*)(Bs + br * BN_ + bc) = *(const float4*)(B + (size_t)(k0 + br) * N + bn0 + bc);
        }
        __syncthreads();
#pragma unroll
        for (int k = 0; k < BK_; k++) {
            float ra[TM_], rb[TN_];
#pragma unroll
            for (int i = 0; i < TM_; i++) ra[i] = As[k * BM_ + tr * TM_ + i];
#pragma unroll
            for (int j = 0; j < TN_; j++) rb[j] = Bs[k * BN_ + tc * TN_ + j];
#pragma unroll
            for (int i = 0; i < TM_; i++)
#pragma unroll
                for (int j = 0; j < TN_; j++) acc[i][j] += ra[i] * rb[j];
        }
        __syncthreads();
    }
#pragma unroll
    for (int i = 0; i < TM_; i++) {
        int row = bm0 + tr * TM_ + i;
        if (row >= M) continue;
#pragma unroll
        for (int j = 0; j < TN_; j += 4) {
            int col = bn0 + tc * TN_ + j;
            float4 v = make_float4(acc[i][j], acc[i][j + 1], acc[i][j + 2], acc[i][j + 3]);
            if (bias) {
                float4 bb = *(const float4*)(bias + col);
                v.x += bb.x; v.y += bb.y; v.z += bb.z; v.w += bb.w;
            }
            if (relu) {
                v.x = fmaxf(v.x, 0.f); v.y = fmaxf(v.y, 0.f);
                v.z = fmaxf(v.z, 0.f); v.w = fmaxf(v.w, 0.f);
            }
            *(float4*)(C + (size_t)row * N + col) = v;
        }
    }
}

// ---------------- pooling + head ----------------
__global__ void zero_f_k(float* p, int n) {
    int i = blockIdx.x * blockDim.x + threadIdx.x;
    if (i < n) p[i] = 0.f;
}
__global__ void pool_k(const int* __restrict__ batch) {
    int idx = blockIdx.x * blockDim.x + threadIdx.x;
    if (idx >= NN * 64) return;
    int n = idx >> 6, c = idx & 63;
    int bg = batch[n];
    float4 v = *(const float4*)(g_hnew + (size_t)n * DD + c * 4);
    float* d = g_pool + (size_t)bg * DD + c * 4;
    atomicAdd(d + 0, v.x); atomicAdd(d + 1, v.y);
    atomicAdd(d + 2, v.z); atomicAdd(d + 3, v.w);
}
__global__ void out_k(const float* __restrict__ W, const float* __restrict__ b,
                      float* __restrict__ out) {
    int g = blockIdx.x;
    int t = threadIdx.x;
    float4 z = *(const float4*)(g_z2 + (size_t)g * 512 + t * 4);
    float4 w = *(const float4*)(W + t * 4);
    float s = z.x * w.x + z.y * w.y + z.z * w.z + z.w * w.w;
#pragma unroll
    for (int o = 16; o > 0; o >>= 1) s += __shfl_down_sync(0xffffffffu, s, o);
    __shared__ float sm[4];
    if ((t & 31) == 0) sm[t >> 5] = s;
    __syncthreads();
    if (t == 0) out[g] = fmaxf(sm[0] + sm[1] + sm[2] + sm[3] + b[0], 0.f);
}

// ---------------- launch ----------------
extern "C" void kernel_launch(void* const* d_in, const int* in_sizes, int n_in,
                              void* d_out, int out_size) {
    const float* x      = (const float*)d_in[0];
    const int*   ei     = (const int*)d_in[1];
    const int*   et     = (const int*)d_in[2];
    const int*   batch  = (const int*)d_in[3];
    const float* encW   = (const float*)d_in[4];
    const float* encb   = (const float*)d_in[5];
    const float* preluA = (const float*)d_in[6];
    const float* relW   = (const float*)d_in[7];
    const float* rootW  = (const float*)d_in[8];
    const float* convb  = (const float*)d_in[9];
    const float* gpW1   = (const float*)d_in[10];
    const float* gpb1   = (const float*)d_in[11];
    const float* gpW2   = (const float*)d_in[12];
    const float* gpb2   = (const float*)d_in[13];
    const float* fcW1   = (const float*)d_in[14];
    const float* fcb1   = (const float*)d_in[15];
    const float* fcW2   = (const float*)d_in[16];
    const float* fcb2   = (const float*)d_in[17];
    const float* outW   = (const float*)d_in[18];
    const float* outb   = (const float*)d_in[19];
    float*       out    = (float*)d_out;

    float *p_h, *p_hnew, *p_t1, *p_pool, *p_z1, *p_z2, *p_deg;
    cudaGetSymbolAddress((void**)&p_h, g_h);
    cudaGetSymbolAddress((void**)&p_hnew, g_hnew);
    cudaGetSymbolAddress((void**)&p_t1, g_t1);
    cudaGetSymbolAddress((void**)&p_pool, g_pool);
    cudaGetSymbolAddress((void**)&p_z1, g_z1);
    cudaGetSymbolAddress((void**)&p_z2, g_z2);
    cudaGetSymbolAddress((void**)&p_deg, g_deg);

    // encoder
    encoder_k<<<NN, 256>>>(x, encW, encb);

    // CSR by dst (edges invariant across layers)
    zero_i_k<<<(NN + 255) / 256, 256>>>((int*)p_deg, NN);
    hist_k<<<(NE + 255) / 256, 256>>>(ei);
    scan_k<<<1, 1024>>>();
    scatter_k<<<(NE + 255) / 256, 256>>>(ei, et);

    // 8 RGCN layers
    for (int l = 0; l < NL; l++) {
        convA_k<<<(NN * DD + 255) / 256, 256>>>();
        convB_k<<<(NC * KK + 255) / 256, 256>>>(relW, rootW, l);
        mma_k<<<dim3(NTM, MT), 256>>>(NN);
        gather_k<<<NN, 64>>>(convb + (size_t)l * DD, preluA);
    }

    // graph head
    dim3 gDD(DD / 128, (NN + 127) / 128);
    sgemm_k<128, 128, 16, 8, 8><<<gDD, 256>>>(p_h, gpW1, p_t1, NN, DD, DD, gpb1, 1);
    sgemm_k<128, 128, 16, 8, 8><<<gDD, 256>>>(p_t1, gpW2, p_hnew, NN, DD, DD, gpb2, 0);

    zero_f_k<<<(NG * DD + 255) / 256, 256>>>(p_pool, NG * DD);
    pool_k<<<(NN * 64 + 255) / 256, 256>>>(batch);

    sgemm_k<64, 64, 16, 4, 4><<<dim3(1024 / 64, NG / 64), 256>>>(
        p_pool, fcW1, p_z1, NG, 1024, DD, fcb1, 1);
    sgemm_k<64, 64, 16, 4, 4><<<dim3(512 / 64, NG / 64), 256>>>(
        p_z1, fcW2, p_z2, NG, 512, 1024, fcb2, 1);
    out_k<<<NG, 128>>>(outW, outb, out);
}

// round 9
// speedup vs baseline: 2.9735x; 1.0184x over previous
#include <cuda_runtime.h>
#include <cuda_bf16.h>
#include <cstdint>

#define NN   50000
#define NE   800000
#define NREL 6
#define NL   8
#define DD   256
#define NG   512
#define KK   768          // tripled K for bf16 split: [hi|lo|hi]
#define NC   1792         // 7*256 (6 rel + root)
#define BM   128
#define BNT  128
#define BK   32
#define MT   391          // ceil(50000/128)
#define NTM  14           // 1792/128
#define SCAT_BLKS  ((NE + 255) / 256)
#define CONVB_ELEMS ((size_t)NL * NC * KK)
#define CONVB_BLKS ((int)((CONVB_ELEMS + 255) / 256))

// ---------------- scratch ----------------
__device__ float          g_h   [(size_t)NN * DD];
__device__ float          g_hnew[(size_t)NN * DD];
__device__ float          g_t1  [(size_t)NN * DD];
__device__ float          g_xW  [(size_t)NN * NC];      // 358 MB
__device__ __nv_bfloat16  g_Ahl [(size_t)NN * KK];      // 76.8 MB
__device__ __nv_bfloat16  g_Bt8 [CONVB_ELEMS];          // 22 MB (all 8 layers)
__device__ int            g_deg [NN];
__device__ int            g_rowptr[NN + 1];
__device__ int            g_cursor[NN];
__device__ unsigned       g_epack[NE];
__device__ float          g_pool[NG * DD];
__device__ float          g_z1  [NG * 1024];
__device__ float          g_z2  [NG * 512];

// ---------------- PTX helpers (baseline ISA only) ----------------
__device__ __forceinline__ uint32_t smem_u32(const void* p) {
    uint32_t a;
    asm("{ .reg .u64 t; cvta.to.shared.u64 t, %1; cvt.u32.u64 %0, t; }" : "=r"(a) : "l"(p));
    return a;
}
__device__ __forceinline__ void cp16(uint32_t s, const void* g) {
    asm volatile("cp.async.cg.shared.global [%0], [%1], 16;" :: "r"(s), "l"(g) : "memory");
}
__device__ __forceinline__ void cp_commit() {
    asm volatile("cp.async.commit_group;" ::: "memory");
}
template <int N>
__device__ __forceinline__ void cp_wait() {
    asm volatile("cp.async.wait_group %0;" :: "n"(N) : "memory");
}
__device__ __forceinline__ void ldsm4(uint32_t a, uint32_t* r) {
    asm volatile("ldmatrix.sync.aligned.m8n8.x4.shared.b16 {%0,%1,%2,%3}, [%4];"
                 : "=r"(r[0]), "=r"(r[1]), "=r"(r[2]), "=r"(r[3]) : "r"(a));
}
__device__ __forceinline__ void mma16816(float* c, const uint32_t* a, const uint32_t* b) {
    asm volatile(
        "mma.sync.aligned.m16n8k16.row.col.f32.bf16.bf16.f32 "
        "{%0,%1,%2,%3}, {%4,%5,%6,%7}, {%8,%9}, {%0,%1,%2,%3};"
        : "+f"(c[0]), "+f"(c[1]), "+f"(c[2]), "+f"(c[3])
        : "r"(a[0]), "r"(a[1]), "r"(a[2]), "r"(a[3]), "r"(b[0]), "r"(b[1]));
}
__device__ __forceinline__ int SW(int row, int cb) {
    return row * 64 + (cb ^ (((row >> 1) & 3) << 4));
}
// write 4 fp32 as hi/lo/hi bf16 split into Ahl row
__device__ __forceinline__ void write_split(__nv_bfloat16* arow, int c0, float4 v) {
    __nv_bfloat162 h0, h1, l0, l1;
    h0.x = __float2bfloat16(v.x); h0.y = __float2bfloat16(v.y);
    h1.x = __float2bfloat16(v.z); h1.y = __float2bfloat16(v.w);
    l0.x = __float2bfloat16(v.x - __bfloat162float(h0.x));
    l0.y = __float2bfloat16(v.y - __bfloat162float(h0.y));
    l1.x = __float2bfloat16(v.z - __bfloat162float(h1.x));
    l1.y = __float2bfloat16(v.w - __bfloat162float(h1.y));
    *(__nv_bfloat162*)(arow + c0)       = h0; *(__nv_bfloat162*)(arow + c0 + 2)       = h1;
    *(__nv_bfloat162*)(arow + 256 + c0) = l0; *(__nv_bfloat162*)(arow + 256 + c0 + 2) = l1;
    *(__nv_bfloat162*)(arow + 512 + c0) = h0; *(__nv_bfloat162*)(arow + 512 + c0 + 2) = h1;
}

// ---------------- encoder (+ zero deg, + layer-0 A split) ----------------
__global__ void encoder_k(const float* __restrict__ x, const float* __restrict__ W,
                          const float* __restrict__ b) {
    int n = blockIdx.x;
    if (threadIdx.x == 0) g_deg[n] = 0;
    __shared__ float xr[13];
    if (threadIdx.x < 13) xr[threadIdx.x] = x[n * 13 + threadIdx.x];
    __syncthreads();
    int d = threadIdx.x;
    float s = b[d];
#pragma unroll
    for (int k = 0; k < 13; k++) s += xr[k] * W[k * DD + d];
    g_h[(size_t)n * DD + d] = s;
    __nv_bfloat16 hi = __float2bfloat16(s);
    __nv_bfloat16 lo = __float2bfloat16(s - __bfloat162float(hi));
    __nv_bfloat16* a = g_Ahl + (size_t)n * KK;
    a[d] = hi; a[256 + d] = lo; a[512 + d] = hi;
}

// ---------------- CSR: hist, coalesced single-block scan, scatter(+convB all layers) --------
__global__ void hist_k(const int* __restrict__ ei) {
    int e = blockIdx.x * blockDim.x + threadIdx.x;
    if (e < NE) atomicAdd(&g_deg[ei[NE + e]], 1);
}
__global__ void scan_k() {
    __shared__ int wsum[32];
    __shared__ int s_run;
    int t = threadIdx.x, lane = t & 31, w = t >> 5;
    if (t == 0) s_run = 0;
    __syncthreads();
    for (int base = 0; base < NN; base += 1024) {
        int i = base + t;
        int v = (i < NN) ? g_deg[i] : 0;
        int xv = v;
#pragma unroll
        for (int o = 1; o < 32; o <<= 1) {
            int y = __shfl_up_sync(0xffffffffu, xv, o);
            if (lane >= o) xv += y;
        }
        if (lane == 31) wsum[w] = xv;
        __syncthreads();
        if (w == 0) {
            int z = wsum[lane];
#pragma unroll
            for (int o = 1; o < 32; o <<= 1) {
                int y = __shfl_up_sync(0xffffffffu, z, o);
                if (lane >= o) z += y;
            }
            wsum[lane] = z;
        }
        __syncthreads();
        int incl = xv + (w > 0 ? wsum[w - 1] : 0) + s_run;
        if (i < NN) { g_rowptr[i] = incl - v; g_cursor[i] = incl - v; }
        __syncthreads();
        if (t == 1023) s_run = incl;
        __syncthreads();
    }
    if (t == 0) g_rowptr[NN] = s_run;
}
__global__ void scatter_convB_k(const int* __restrict__ ei, const int* __restrict__ et,
                                const float* __restrict__ relW, const float* __restrict__ rootW) {
    int b = blockIdx.x;
    if (b < SCAT_BLKS) {
        int e = b * 256 + threadIdx.x;
        if (e >= NE) return;
        int dst = ei[NE + e];
        int pos = atomicAdd(&g_cursor[dst], 1);
        g_epack[pos] = (unsigned)ei[e] | ((unsigned)et[e] << 17);   // src:17 bits, type:3
    } else {
        size_t idx = (size_t)(b - SCAT_BLKS) * 256 + threadIdx.x;
        if (idx >= CONVB_ELEMS) return;
        int l = (int)(idx / ((size_t)NC * KK));
        int r2 = (int)(idx % ((size_t)NC * KK));
        int n = r2 / KK, k = r2 - n * KK;
        int kk = (k < 256) ? k : ((k < 512) ? k - 256 : k - 512);
        float wv;
        if (n < 1536) {
            int r = n >> 8, c = n & 255;
            wv = relW[((((size_t)l * NREL + r) * DD + kk) * DD) + c];
        } else {
            wv = rootW[(((size_t)l * DD + kk) * DD) + (n - 1536)];
        }
        __nv_bfloat16 hi = __float2bfloat16(wv);
        g_Bt8[idx] = (k < 512) ? hi : __float2bfloat16(wv - __bfloat162float(hi));
    }
}

// ---------------- bf16 mma.sync GEMM (3-stage pipeline): g_xW = Ahl @ Bt^T --------------
__global__ __launch_bounds__(256, 2) void mma_k(int M, int layer) {
    __shared__ __align__(16) unsigned char sA[3][BM * 64];    // 3 x 8 KB
    __shared__ __align__(16) unsigned char sB[3][BNT * 64];   // 3 x 8 KB (total 48KB)

    int tid = threadIdx.x, lane = tid & 31, wid = tid >> 5;
    int wm = (wid & 3) * 32;
    int wn = (wid >> 2) * 64;
    int bm0 = blockIdx.y * BM, bn0 = blockIdx.x * BNT;

    uint32_t aA[3] = {smem_u32(sA[0]), smem_u32(sA[1]), smem_u32(sA[2])};
    uint32_t aB[3] = {smem_u32(sB[0]), smem_u32(sB[1]), smem_u32(sB[2])};

    float acc[2][8][4];
#pragma unroll
    for (int i = 0; i < 2; i++)
#pragma unroll
        for (int j = 0; j < 8; j++)
#pragma unroll
            for (int q = 0; q < 4; q++) acc[i][j][q] = 0.f;

    const __nv_bfloat16* A = g_Ahl;
    const __nv_bfloat16* B = g_Bt8 + (size_t)layer * NC * KK;

    auto load_stage = [&](int buf, int kc) {
#pragma unroll
        for (int i = 0; i < 2; i++) {
            int id = tid + i * 256;
            int row = id >> 2, cb = (id & 3) * 16;
            int gr = min(bm0 + row, M - 1);
            cp16(aA[buf] + SW(row, cb), A + (size_t)gr * KK + kc * BK + cb / 2);
        }
#pragma unroll
        for (int i = 0; i < 2; i++) {
            int id = tid + i * 256;
            int row = id >> 2, cb = (id & 3) * 16;
            cp16(aB[buf] + SW(row, cb), B + (size_t)(bn0 + row) * KK + kc * BK + cb / 2);
        }
        cp_commit();
    };

    const int NKC = KK / BK;  // 24
    load_stage(0, 0);
    load_stage(1, 1);

    for (int kc = 0; kc < NKC; kc++) {
        if (kc == NKC - 1) cp_wait<0>(); else cp_wait<1>();
        __syncthreads();                       // stage kc ready; all warps done with buf (kc-1)%3
        if (kc + 2 < NKC) load_stage((kc + 2) % 3, kc + 2);
        int buf = kc % 3;

#pragma unroll
        for (int kkx = 0; kkx < 2; kkx++) {
            uint32_t areg[2][4];
#pragma unroll
            for (int mt = 0; mt < 2; mt++) {
                int row = wm + mt * 16 + (lane & 15);
                int cb = kkx * 32 + ((lane >> 4) << 4);
                ldsm4(aA[buf] + SW(row, cb), areg[mt]);
            }
            uint32_t breg[8][2];
#pragma unroll
            for (int np = 0; np < 4; np++) {
                int row = wn + np * 16 + ((lane >> 4) << 3) + (lane & 7);
                int cb = kkx * 32 + (((lane >> 3) & 1) << 4);
                uint32_t r4[4];
                ldsm4(aB[buf] + SW(row, cb), r4);
                breg[np * 2 + 0][0] = r4[0]; breg[np * 2 + 0][1] = r4[1];
                breg[np * 2 + 1][0] = r4[2]; breg[np * 2 + 1][1] = r4[3];
            }
#pragma unroll
            for (int mt = 0; mt < 2; mt++)
#pragma unroll
                for (int nt = 0; nt < 8; nt++)
                    mma16816(acc[mt][nt], areg[mt], breg[nt]);
        }
        __syncthreads();                       // all warps done reading buf before it is reloaded
    }

#pragma unroll
    for (int mt = 0; mt < 2; mt++) {
        int r0 = bm0 + wm + mt * 16 + (lane >> 2);
#pragma unroll
        for (int nt = 0; nt < 8; nt++) {
            int cn = bn0 + wn + nt * 8 + (lane & 3) * 2;
            if (r0 < M)
                *(float2*)(g_xW + (size_t)r0 * NC + cn) = make_float2(acc[mt][nt][0], acc[mt][nt][1]);
            if (r0 + 8 < M)
                *(float2*)(g_xW + (size_t)(r0 + 8) * NC + cn) = make_float2(acc[mt][nt][2], acc[mt][nt][3]);
        }
    }
}

// ------- fused gather + root + skip + bias + PReLU + L2 norm + next-layer A split -------
__global__ void gather_k(const float* __restrict__ convb, const float* __restrict__ pa) {
    int row = blockIdx.x;
    int t = threadIdx.x;   // 64 threads, 4 cols each
    const float* xwr = g_xW + (size_t)row * NC;
    float4 acc = *(const float4*)(xwr + 1536 + t * 4);                 // root
    float4 h0  = *(const float4*)(g_h + (size_t)row * DD + t * 4);     // skip
    float4 cb  = *(const float4*)(convb + t * 4);
    acc.x += h0.x + cb.x; acc.y += h0.y + cb.y; acc.z += h0.z + cb.z; acc.w += h0.w + cb.w;
    int beg = g_rowptr[row], end = g_rowptr[row + 1];
    for (int i = beg; i < end; i++) {
        unsigned p = g_epack[i];
        int src = p & 0x1FFFF, typ = (p >> 17) & 7;
        float4 m = *(const float4*)(g_xW + (size_t)src * NC + typ * DD + t * 4);
        acc.x += m.x; acc.y += m.y; acc.z += m.z; acc.w += m.w;
    }
    float a = *pa;
    acc.x = acc.x > 0.f ? acc.x : a * acc.x;
    acc.y = acc.y > 0.f ? acc.y : a * acc.y;
    acc.z = acc.z > 0.f ? acc.z : a * acc.z;
    acc.w = acc.w > 0.f ? acc.w : a * acc.w;
    float s = acc.x * acc.x + acc.y * acc.y + acc.z * acc.z + acc.w * acc.w;
#pragma unroll
    for (int o = 16; o > 0; o >>= 1) s += __shfl_down_sync(0xffffffffu, s, o);
    __shared__ float sm[2];
    if ((t & 31) == 0) sm[t >> 5] = s;
    __syncthreads();
    float inv = 1.f / fmaxf(sqrtf(sm[0] + sm[1]), 1e-12f);
    acc.x *= inv; acc.y *= inv; acc.z *= inv; acc.w *= inv;
    *(float4*)(g_h + (size_t)row * DD + t * 4) = acc;
    write_split(g_Ahl + (size_t)row * KK, t * 4, acc);   // next layer's A''
}

// ---------------- fp32 SGEMM (head) ----------------
template <int BM_, int BN_, int BK_, int TM_, int TN_>
__global__ __launch_bounds__((BM_ / TM_) * (BN_ / TN_))
void sgemm_k(const float* __restrict__ A, const float* __restrict__ B,
             float* __restrict__ C, int M, int N, int K,
             const float* __restrict__ bias, int relu) {
    constexpr int NT = (BM_ / TM_) * (BN_ / TN_);
    __shared__ float As[BK_ * BM_];
    __shared__ float Bs[BK_ * BN_];
    int tid = threadIdx.x;
    int bm0 = blockIdx.y * BM_, bn0 = blockIdx.x * BN_;
    int tr = tid / (BN_ / TN_), tc = tid % (BN_ / TN_);
    float acc[TM_][TN_];
#pragma unroll
    for (int i = 0; i < TM_; i++)
#pragma unroll
        for (int j = 0; j < TN_; j++) acc[i][j] = 0.f;
    constexpr int AIT = (BM_ * BK_ / 4) / NT;
    constexpr int BIT = (BK_ * BN_ / 4) / NT;
    for (int k0 = 0; k0 < K; k0 += BK_) {
#pragma unroll
        for (int it = 0; it < AIT; it++) {
            int i = tid + it * NT;
            int ar = i / (BK_ / 4), ac = (i % (BK_ / 4)) * 4;
            float4 v = make_float4(0.f, 0.f, 0.f, 0.f);
            int gr = bm0 + ar;
            if (gr < M) v = *(const float4*)(A + (size_t)gr * K + k0 + ac);
            As[(ac + 0) * BM_ + ar] = v.x; As[(ac + 1) * BM_ + ar] = v.y;
            As[(ac + 2) * BM_ + ar] = v.z; As[(ac + 3) * BM_ + ar] = v.w;
        }
#pragma unroll
        for (int it = 0; it < BIT; it++) {
            int i = tid + it * NT;
            int br = i / (BN_ / 4), bc = (i % (BN_ / 4)) * 4;
            *(float4*)(Bs + br * BN_ + bc) = *(const float4*)(B + (size_t)(k0 + br) * N + bn0 + bc);
        }
        __syncthreads();
#pragma unroll
        for (int k = 0; k < BK_; k++) {
            float ra[TM_], rb[TN_];
#pragma unroll
            for (int i = 0; i < TM_; i++) ra[i] = As[k * BM_ + tr * TM_ + i];
#pragma unroll
            for (int j = 0; j < TN_; j++) rb[j] = Bs[k * BN_ + tc * TN_ + j];
#pragma unroll
            for (int i = 0; i < TM_; i++)
#pragma unroll
                for (int j = 0; j < TN_; j++) acc[i][j] += ra[i] * rb[j];
        }
        __syncthreads();
    }
#pragma unroll
    for (int i = 0; i < TM_; i++) {
        int row = bm0 + tr * TM_ + i;
        if (row >= M) continue;
#pragma unroll
        for (int j = 0; j < TN_; j += 4) {
            int col = bn0 + tc * TN_ + j;
            float4 v = make_float4(acc[i][j], acc[i][j + 1], acc[i][j + 2], acc[i][j + 3]);
            if (bias) {
                float4 bb = *(const float4*)(bias + col);
                v.x += bb.x; v.y += bb.y; v.z += bb.z; v.w += bb.w;
            }
            if (relu) {
                v.x = fmaxf(v.x, 0.f); v.y = fmaxf(v.y, 0.f);
                v.z = fmaxf(v.z, 0.f); v.w = fmaxf(v.w, 0.f);
            }
            *(float4*)(C + (size_t)row * N + col) = v;
        }
    }
}

// ---------------- pooling + head ----------------
__global__ void zero_f_k(float* p, int n) {
    int i = blockIdx.x * blockDim.x + threadIdx.x;
    if (i < n) p[i] = 0.f;
}
__global__ void pool_k(const int* __restrict__ batch) {
    int idx = blockIdx.x * blockDim.x + threadIdx.x;
    if (idx >= NN * 64) return;
    int n = idx >> 6, c = idx & 63;
    int bg = batch[n];
    float4 v = *(const float4*)(g_hnew + (size_t)n * DD + c * 4);
    float* d = g_pool + (size_t)bg * DD + c * 4;
    atomicAdd(d + 0, v.x); atomicAdd(d + 1, v.y);
    atomicAdd(d + 2, v.z); atomicAdd(d + 3, v.w);
}
__global__ void out_k(const float* __restrict__ W, const float* __restrict__ b,
                      float* __restrict__ out) {
    int g = blockIdx.x;
    int t = threadIdx.x;
    float4 z = *(const float4*)(g_z2 + (size_t)g * 512 + t * 4);
    float4 w = *(const float4*)(W + t * 4);
    float s = z.x * w.x + z.y * w.y + z.z * w.z + z.w * w.w;
#pragma unroll
    for (int o = 16; o > 0; o >>= 1) s += __shfl_down_sync(0xffffffffu, s, o);
    __shared__ float sm[4];
    if ((t & 31) == 0) sm[t >> 5] = s;
    __syncthreads();
    if (t == 0) out[g] = fmaxf(sm[0] + sm[1] + sm[2] + sm[3] + b[0], 0.f);
}

// ---------------- launch ----------------
extern "C" void kernel_launch(void* const* d_in, const int* in_sizes, int n_in,
                              void* d_out, int out_size) {
    const float* x      = (const float*)d_in[0];
    const int*   ei     = (const int*)d_in[1];
    const int*   et     = (const int*)d_in[2];
    const int*   batch  = (const int*)d_in[3];
    const float* encW   = (const float*)d_in[4];
    const float* encb   = (const float*)d_in[5];
    const float* preluA = (const float*)d_in[6];
    const float* relW   = (const float*)d_in[7];
    const float* rootW  = (const float*)d_in[8];
    const float* convb  = (const float*)d_in[9];
    const float* gpW1   = (const float*)d_in[10];
    const float* gpb1   = (const float*)d_in[11];
    const float* gpW2   = (const float*)d_in[12];
    const float* gpb2   = (const float*)d_in[13];
    const float* fcW1   = (const float*)d_in[14];
    const float* fcb1   = (const float*)d_in[15];
    const float* fcW2   = (const float*)d_in[16];
    const float* fcb2   = (const float*)d_in[17];
    const float* outW   = (const float*)d_in[18];
    const float* outb   = (const float*)d_in[19];
    float*       out    = (float*)d_out;

    float *p_h, *p_hnew, *p_t1, *p_pool, *p_z1, *p_z2;
    cudaGetSymbolAddress((void**)&p_h, g_h);
    cudaGetSymbolAddress((void**)&p_hnew, g_hnew);
    cudaGetSymbolAddress((void**)&p_t1, g_t1);
    cudaGetSymbolAddress((void**)&p_pool, g_pool);
    cudaGetSymbolAddress((void**)&p_z1, g_z1);
    cudaGetSymbolAddress((void**)&p_z2, g_z2);

    // encoder (+ deg zero + layer-0 A'')
    encoder_k<<<NN, 256>>>(x, encW, encb);

    // CSR + all-layer B'' (edges/weights invariant across layers)
    hist_k<<<(NE + 255) / 256, 256>>>(ei);
    scan_k<<<1, 1024>>>();
    scatter_convB_k<<<SCAT_BLKS + CONVB_BLKS, 256>>>(ei, et, relW, rootW);

    // 8 RGCN layers
    for (int l = 0; l < NL; l++) {
        mma_k<<<dim3(NTM, MT), 256>>>(NN, l);
        gather_k<<<NN, 64>>>(convb + (size_t)l * DD, preluA);
    }

    // graph head
    dim3 gDD(DD / 128, (NN + 127) / 128);
    sgemm_k<128, 128, 16, 8, 8><<<gDD, 256>>>(p_h, gpW1, p_t1, NN, DD, DD, gpb1, 1);
    sgemm_k<128, 128, 16, 8, 8><<<gDD, 256>>>(p_t1, gpW2, p_hnew, NN, DD, DD, gpb2, 0);

    zero_f_k<<<(NG * DD + 255) / 256, 256>>>(p_pool, NG * DD);
    pool_k<<<(NN * 64 + 255) / 256, 256>>>(batch);

    sgemm_k<64, 64, 16, 4, 4><<<dim3(1024 / 64, NG / 64), 256>>>(
        p_pool, fcW1, p_z1, NG, 1024, DD, fcb1, 1);
    sgemm_k<64, 64, 16, 4, 4><<<dim3(512 / 64, NG / 64), 256>>>(
        p_z1, fcW2, p_z2, NG, 512, 1024, fcb2, 1);
    out_k<<<NG, 128>>>(outW, outb, out);
}

// round 10
// speedup vs baseline: 5.8573x; 1.9698x over previous
#include <cuda_runtime.h>
#include <cuda_fp16.h>
#include <cstdint>

#define NN   50000
#define NE   800000
#define NREL 6
#define NL   8
#define DD   256
#define NG   512
#define KA   256          // GEMM K (single-pass fp16, no split)
#define NC   1792         // 7*256 (6 rel + root)
#define BM   128
#define BNT  128
#define BK   32
#define MT   391          // ceil(50000/128)
#define NTM  14           // 1792/128
#define SCAT_BLKS  ((NE + 255) / 256)
#define CONVB_ELEMS ((size_t)NL * NC * KA)
#define CONVB_BLKS ((int)((CONVB_ELEMS + 255) / 256))

// ---------------- scratch ----------------
__device__ float   g_h   [(size_t)NN * DD];      //  51 MB fp32 hidden state
__device__ float   g_hnew[(size_t)NN * DD];
__device__ float   g_t1  [(size_t)NN * DD];
__device__ __half  g_xWh [(size_t)NN * NC];      // 179 MB fp16 transformed features
__device__ __half  g_Ah  [(size_t)NN * KA];      //  25.6 MB fp16 A (L2-resident)
__device__ __half  g_B8  [CONVB_ELEMS];          //   7.3 MB fp16 all-layer weights
__device__ int     g_deg [NN];
__device__ int     g_rowptr[NN + 1];
__device__ int     g_cursor[NN];
__device__ unsigned g_epack[NE];
__device__ float   g_pool[NG * DD];
__device__ float   g_z1  [NG * 1024];
__device__ float   g_z2  [NG * 512];

// ---------------- PTX helpers (baseline ISA only) ----------------
__device__ __forceinline__ uint32_t smem_u32(const void* p) {
    uint32_t a;
    asm("{ .reg .u64 t; cvta.to.shared.u64 t, %1; cvt.u32.u64 %0, t; }" : "=r"(a) : "l"(p));
    return a;
}
__device__ __forceinline__ void cp16(uint32_t s, const void* g) {
    asm volatile("cp.async.cg.shared.global [%0], [%1], 16;" :: "r"(s), "l"(g) : "memory");
}
__device__ __forceinline__ void cp_commit() {
    asm volatile("cp.async.commit_group;" ::: "memory");
}
template <int N>
__device__ __forceinline__ void cp_wait() {
    asm volatile("cp.async.wait_group %0;" :: "n"(N) : "memory");
}
__device__ __forceinline__ void ldsm4(uint32_t a, uint32_t* r) {
    asm volatile("ldmatrix.sync.aligned.m8n8.x4.shared.b16 {%0,%1,%2,%3}, [%4];"
                 : "=r"(r[0]), "=r"(r[1]), "=r"(r[2]), "=r"(r[3]) : "r"(a));
}
__device__ __forceinline__ void mma16816(float* c, const uint32_t* a, const uint32_t* b) {
    asm volatile(
        "mma.sync.aligned.m16n8k16.row.col.f32.f16.f16.f32 "
        "{%0,%1,%2,%3}, {%4,%5,%6,%7}, {%8,%9}, {%0,%1,%2,%3};"
        : "+f"(c[0]), "+f"(c[1]), "+f"(c[2]), "+f"(c[3])
        : "r"(a[0]), "r"(a[1]), "r"(a[2]), "r"(a[3]), "r"(b[0]), "r"(b[1]));
}
__device__ __forceinline__ int SW(int row, int cb) {
    return row * 64 + (cb ^ (((row >> 1) & 3) << 4));
}

// ---------------- encoder (+ zero deg, + layer-0 fp16 A) ----------------
__global__ void encoder_k(const float* __restrict__ x, const float* __restrict__ W,
                          const float* __restrict__ b) {
    int n = blockIdx.x;
    if (threadIdx.x == 0) g_deg[n] = 0;
    __shared__ float xr[13];
    if (threadIdx.x < 13) xr[threadIdx.x] = x[n * 13 + threadIdx.x];
    __syncthreads();
    int d = threadIdx.x;
    float s = b[d];
#pragma unroll
    for (int k = 0; k < 13; k++) s += xr[k] * W[k * DD + d];
    g_h[(size_t)n * DD + d] = s;
    g_Ah[(size_t)n * KA + d] = __float2half(s);
}

// ---------------- CSR: hist, coalesced scan, scatter(+all-layer fp16 B) --------
__global__ void hist_k(const int* __restrict__ ei) {
    int e = blockIdx.x * blockDim.x + threadIdx.x;
    if (e < NE) atomicAdd(&g_deg[ei[NE + e]], 1);
}
__global__ void scan_k() {
    __shared__ int wsum[32];
    __shared__ int s_run;
    int t = threadIdx.x, lane = t & 31, w = t >> 5;
    if (t == 0) s_run = 0;
    __syncthreads();
    for (int base = 0; base < NN; base += 1024) {
        int i = base + t;
        int v = (i < NN) ? g_deg[i] : 0;
        int xv = v;
#pragma unroll
        for (int o = 1; o < 32; o <<= 1) {
            int y = __shfl_up_sync(0xffffffffu, xv, o);
            if (lane >= o) xv += y;
        }
        if (lane == 31) wsum[w] = xv;
        __syncthreads();
        if (w == 0) {
            int z = wsum[lane];
#pragma unroll
            for (int o = 1; o < 32; o <<= 1) {
                int y = __shfl_up_sync(0xffffffffu, z, o);
                if (lane >= o) z += y;
            }
            wsum[lane] = z;
        }
        __syncthreads();
        int incl = xv + (w > 0 ? wsum[w - 1] : 0) + s_run;
        if (i < NN) { g_rowptr[i] = incl - v; g_cursor[i] = incl - v; }
        __syncthreads();
        if (t == 1023) s_run = incl;
        __syncthreads();
    }
    if (t == 0) g_rowptr[NN] = s_run;
}
__global__ void scatter_convB_k(const int* __restrict__ ei, const int* __restrict__ et,
                                const float* __restrict__ relW, const float* __restrict__ rootW) {
    int b = blockIdx.x;
    if (b < SCAT_BLKS) {
        int e = b * 256 + threadIdx.x;
        if (e >= NE) return;
        int dst = ei[NE + e];
        int pos = atomicAdd(&g_cursor[dst], 1);
        g_epack[pos] = (unsigned)ei[e] | ((unsigned)et[e] << 17);   // src:17 bits, type:3
    } else {
        size_t idx = (size_t)(b - SCAT_BLKS) * 256 + threadIdx.x;
        if (idx >= CONVB_ELEMS) return;
        int l = (int)(idx / ((size_t)NC * KA));
        int r2 = (int)(idx % ((size_t)NC * KA));
        int n = r2 / KA, k = r2 - n * KA;
        float wv;
        if (n < 1536) {
            int r = n >> 8, c = n & 255;
            wv = relW[((((size_t)l * NREL + r) * DD + k) * DD) + c];
        } else {
            wv = rootW[(((size_t)l * DD + k) * DD) + (n - 1536)];
        }
        g_B8[idx] = __float2half(wv);
    }
}

// ---------------- fp16 mma.sync GEMM (3-stage): g_xWh = Ah @ B8[l]^T --------------
__global__ __launch_bounds__(256, 2) void mma_k(int M, int layer) {
    __shared__ __align__(16) unsigned char sA[3][BM * 64];    // 3 x 8 KB
    __shared__ __align__(16) unsigned char sB[3][BNT * 64];   // 3 x 8 KB

    int tid = threadIdx.x, lane = tid & 31, wid = tid >> 5;
    int wm = (wid & 3) * 32;
    int wn = (wid >> 2) * 64;
    int bm0 = blockIdx.y * BM, bn0 = blockIdx.x * BNT;

    uint32_t aA[3] = {smem_u32(sA[0]), smem_u32(sA[1]), smem_u32(sA[2])};
    uint32_t aB[3] = {smem_u32(sB[0]), smem_u32(sB[1]), smem_u32(sB[2])};

    float acc[2][8][4];
#pragma unroll
    for (int i = 0; i < 2; i++)
#pragma unroll
        for (int j = 0; j < 8; j++)
#pragma unroll
            for (int q = 0; q < 4; q++) acc[i][j][q] = 0.f;

    const __half* A = g_Ah;
    const __half* B = g_B8 + (size_t)layer * NC * KA;

    auto load_stage = [&](int buf, int kc) {
#pragma unroll
        for (int i = 0; i < 2; i++) {
            int id = tid + i * 256;
            int row = id >> 2, cb = (id & 3) * 16;
            int gr = min(bm0 + row, M - 1);
            cp16(aA[buf] + SW(row, cb), A + (size_t)gr * KA + kc * BK + cb / 2);
        }
#pragma unroll
        for (int i = 0; i < 2; i++) {
            int id = tid + i * 256;
            int row = id >> 2, cb = (id & 3) * 16;
            cp16(aB[buf] + SW(row, cb), B + (size_t)(bn0 + row) * KA + kc * BK + cb / 2);
        }
        cp_commit();
    };

    const int NKC = KA / BK;  // 8
    load_stage(0, 0);
    load_stage(1, 1);

    for (int kc = 0; kc < NKC; kc++) {
        if (kc == NKC - 1) cp_wait<0>(); else cp_wait<1>();
        __syncthreads();
        if (kc + 2 < NKC) load_stage((kc + 2) % 3, kc + 2);
        int buf = kc % 3;

#pragma unroll
        for (int kkx = 0; kkx < 2; kkx++) {
            uint32_t areg[2][4];
#pragma unroll
            for (int mt = 0; mt < 2; mt++) {
                int row = wm + mt * 16 + (lane & 15);
                int cb = kkx * 32 + ((lane >> 4) << 4);
                ldsm4(aA[buf] + SW(row, cb), areg[mt]);
            }
            uint32_t breg[8][2];
#pragma unroll
            for (int np = 0; np < 4; np++) {
                int row = wn + np * 16 + ((lane >> 4) << 3) + (lane & 7);
                int cb = kkx * 32 + (((lane >> 3) & 1) << 4);
                uint32_t r4[4];
                ldsm4(aB[buf] + SW(row, cb), r4);
                breg[np * 2 + 0][0] = r4[0]; breg[np * 2 + 0][1] = r4[1];
                breg[np * 2 + 1][0] = r4[2]; breg[np * 2 + 1][1] = r4[3];
            }
#pragma unroll
            for (int mt = 0; mt < 2; mt++)
#pragma unroll
                for (int nt = 0; nt < 8; nt++)
                    mma16816(acc[mt][nt], areg[mt], breg[nt]);
        }
        __syncthreads();
    }

    // epilogue: fp16 to g_xWh
#pragma unroll
    for (int mt = 0; mt < 2; mt++) {
        int r0 = bm0 + wm + mt * 16 + (lane >> 2);
#pragma unroll
        for (int nt = 0; nt < 8; nt++) {
            int cn = bn0 + wn + nt * 8 + (lane & 3) * 2;
            if (r0 < M)
                *(__half2*)(g_xWh + (size_t)r0 * NC + cn) =
                    __floats2half2_rn(acc[mt][nt][0], acc[mt][nt][1]);
            if (r0 + 8 < M)
                *(__half2*)(g_xWh + (size_t)(r0 + 8) * NC + cn) =
                    __floats2half2_rn(acc[mt][nt][2], acc[mt][nt][3]);
        }
    }
}

// ------- fused gather + root + skip + bias + PReLU + L2 norm + next-layer fp16 A -------
__global__ void gather_k(const float* __restrict__ convb, const float* __restrict__ pa) {
    int row = blockIdx.x;
    int t = threadIdx.x;   // 64 threads, 4 cols each
    const __half* xwr = g_xWh + (size_t)row * NC;
    uint2 rr = *(const uint2*)(xwr + 1536 + t * 4);                    // root (4 halves)
    float2 r0 = __half22float2(*(__half2*)&rr.x);
    float2 r1 = __half22float2(*(__half2*)&rr.y);
    float4 acc = make_float4(r0.x, r0.y, r1.x, r1.y);
    float4 h0  = *(const float4*)(g_h + (size_t)row * DD + t * 4);     // skip (fp32)
    float4 cb  = *(const float4*)(convb + t * 4);
    acc.x += h0.x + cb.x; acc.y += h0.y + cb.y; acc.z += h0.z + cb.z; acc.w += h0.w + cb.w;
    int beg = g_rowptr[row], end = g_rowptr[row + 1];
    for (int i = beg; i < end; i++) {
        unsigned p = g_epack[i];
        int src = p & 0x1FFFF, typ = (p >> 17) & 7;
        uint2 mm = *(const uint2*)(g_xWh + (size_t)src * NC + typ * DD + t * 4);
        float2 m0 = __half22float2(*(__half2*)&mm.x);
        float2 m1 = __half22float2(*(__half2*)&mm.y);
        acc.x += m0.x; acc.y += m0.y; acc.z += m1.x; acc.w += m1.y;
    }
    float a = *pa;
    acc.x = acc.x > 0.f ? acc.x : a * acc.x;
    acc.y = acc.y > 0.f ? acc.y : a * acc.y;
    acc.z = acc.z > 0.f ? acc.z : a * acc.z;
    acc.w = acc.w > 0.f ? acc.w : a * acc.w;
    float s = acc.x * acc.x + acc.y * acc.y + acc.z * acc.z + acc.w * acc.w;
#pragma unroll
    for (int o = 16; o > 0; o >>= 1) s += __shfl_down_sync(0xffffffffu, s, o);
    __shared__ float sm[2];
    if ((t & 31) == 0) sm[t >> 5] = s;
    __syncthreads();
    float inv = 1.f / fmaxf(sqrtf(sm[0] + sm[1]), 1e-12f);
    acc.x *= inv; acc.y *= inv; acc.z *= inv; acc.w *= inv;
    *(float4*)(g_h + (size_t)row * DD + t * 4) = acc;
    __half* arow = g_Ah + (size_t)row * KA + t * 4;
    *(__half2*)(arow)     = __floats2half2_rn(acc.x, acc.y);
    *(__half2*)(arow + 2) = __floats2half2_rn(acc.z, acc.w);
}

// ---------------- fp32 SGEMM (head) ----------------
template <int BM_, int BN_, int BK_, int TM_, int TN_>
__global__ __launch_bounds__((BM_ / TM_) * (BN_ / TN_))
void sgemm_k(const float* __restrict__ A, const float* __restrict__ B,
             float* __restrict__ C, int M, int N, int K,
             const float* __restrict__ bias, int relu) {
    constexpr int NT = (BM_ / TM_) * (BN_ / TN_);
    __shared__ float As[BK_ * BM_];
    __shared__ float Bs[BK_ * BN_];
    int tid = threadIdx.x;
    int bm0 = blockIdx.y * BM_, bn0 = blockIdx.x * BN_;
    int tr = tid / (BN_ / TN_), tc = tid % (BN_ / TN_);
    float acc[TM_][TN_];
#pragma unroll
    for (int i = 0; i < TM_; i++)
#pragma unroll
        for (int j = 0; j < TN_; j++) acc[i][j] = 0.f;
    constexpr int AIT = (BM_ * BK_ / 4) / NT;
    constexpr int BIT = (BK_ * BN_ / 4) / NT;
    for (int k0 = 0; k0 < K; k0 += BK_) {
#pragma unroll
        for (int it = 0; it < AIT; it++) {
            int i = tid + it * NT;
            int ar = i / (BK_ / 4), ac = (i % (BK_ / 4)) * 4;
            float4 v = make_float4(0.f, 0.f, 0.f, 0.f);
            int gr = bm0 + ar;
            if (gr < M) v = *(const float4*)(A + (size_t)gr * K + k0 + ac);
            As[(ac + 0) * BM_ + ar] = v.x; As[(ac + 1) * BM_ + ar] = v.y;
            As[(ac + 2) * BM_ + ar] = v.z; As[(ac + 3) * BM_ + ar] = v.w;
        }
#pragma unroll
        for (int it = 0; it < BIT; it++) {
            int i = tid + it * NT;
            int br = i / (BN_ / 4), bc = (i % (BN_ / 4)) * 4;
            *(float4*)(Bs + br * BN_ + bc) = *(const float4*)(B + (size_t)(k0 + br) * N + bn0 + bc);
        }
        __syncthreads();
#pragma unroll
        for (int k = 0; k < BK_; k++) {
            float ra[TM_], rb[TN_];
#pragma unroll
            for (int i = 0; i < TM_; i++) ra[i] = As[k * BM_ + tr * TM_ + i];
#pragma unroll
            for (int j = 0; j < TN_; j++) rb[j] = Bs[k * BN_ + tc * TN_ + j];
#pragma unroll
            for (int i = 0; i < TM_; i++)
#pragma unroll
                for (int j = 0; j < TN_; j++) acc[i][j] += ra[i] * rb[j];
        }
        __syncthreads();
    }
#pragma unroll
    for (int i = 0; i < TM_; i++) {
        int row = bm0 + tr * TM_ + i;
        if (row >= M) continue;
#pragma unroll
        for (int j = 0; j < TN_; j += 4) {
            int col = bn0 + tc * TN_ + j;
            float4 v = make_float4(acc[i][j], acc[i][j + 1], acc[i][j + 2], acc[i][j + 3]);
            if (bias) {
                float4 bb = *(const float4*)(bias + col);
                v.x += bb.x; v.y += bb.y; v.z += bb.z; v.w += bb.w;
            }
            if (relu) {
                v.x = fmaxf(v.x, 0.f); v.y = fmaxf(v.y, 0.f);
                v.z = fmaxf(v.z, 0.f); v.w = fmaxf(v.w, 0.f);
            }
            *(float4*)(C + (size_t)row * N + col) = v;
        }
    }
}

// ---------------- pooling + head ----------------
__global__ void zero_f_k(float* p, int n) {
    int i = blockIdx.x * blockDim.x + threadIdx.x;
    if (i < n) p[i] = 0.f;
}
__global__ void pool_k(const int* __restrict__ batch) {
    int idx = blockIdx.x * blockDim.x + threadIdx.x;
    if (idx >= NN * 64) return;
    int n = idx >> 6, c = idx & 63;
    int bg = batch[n];
    float4 v = *(const float4*)(g_hnew + (size_t)n * DD + c * 4);
    float* d = g_pool + (size_t)bg * DD + c * 4;
    atomicAdd(d + 0, v.x); atomicAdd(d + 1, v.y);
    atomicAdd(d + 2, v.z); atomicAdd(d + 3, v.w);
}
__global__ void out_k(const float* __restrict__ W, const float* __restrict__ b,
                      float* __restrict__ out) {
    int g = blockIdx.x;
    int t = threadIdx.x;
    float4 z = *(const float4*)(g_z2 + (size_t)g * 512 + t * 4);
    float4 w = *(const float4*)(W + t * 4);
    float s = z.x * w.x + z.y * w.y + z.z * w.z + z.w * w.w;
#pragma unroll
    for (int o = 16; o > 0; o >>= 1) s += __shfl_down_sync(0xffffffffu, s, o);
    __shared__ float sm[4];
    if ((t & 31) == 0) sm[t >> 5] = s;
    __syncthreads();
    if (t == 0) out[g] = fmaxf(sm[0] + sm[1] + sm[2] + sm[3] + b[0], 0.f);
}

// ---------------- launch ----------------
extern "C" void kernel_launch(void* const* d_in, const int* in_sizes, int n_in,
                              void* d_out, int out_size) {
    const float* x      = (const float*)d_in[0];
    const int*   ei     = (const int*)d_in[1];
    const int*   et     = (const int*)d_in[2];
    const int*   batch  = (const int*)d_in[3];
    const float* encW   = (const float*)d_in[4];
    const float* encb   = (const float*)d_in[5];
    const float* preluA = (const float*)d_in[6];
    const float* relW   = (const float*)d_in[7];
    const float* rootW  = (const float*)d_in[8];
    const float* convb  = (const float*)d_in[9];
    const float* gpW1   = (const float*)d_in[10];
    const float* gpb1   = (const float*)d_in[11];
    const float* gpW2   = (const float*)d_in[12];
    const float* gpb2   = (const float*)d_in[13];
    const float* fcW1   = (const float*)d_in[14];
    const float* fcb1   = (const float*)d_in[15];
    const float* fcW2   = (const float*)d_in[16];
    const float* fcb2   = (const float*)d_in[17];
    const float* outW   = (const float*)d_in[18];
    const float* outb   = (const float*)d_in[19];
    float*       out    = (float*)d_out;

    float *p_h, *p_hnew, *p_t1, *p_pool, *p_z1, *p_z2;
    cudaGetSymbolAddress((void**)&p_h, g_h);
    cudaGetSymbolAddress((void**)&p_hnew, g_hnew);
    cudaGetSymbolAddress((void**)&p_t1, g_t1);
    cudaGetSymbolAddress((void**)&p_pool, g_pool);
    cudaGetSymbolAddress((void**)&p_z1, g_z1);
    cudaGetSymbolAddress((void**)&p_z2, g_z2);

    // encoder (+ deg zero + layer-0 fp16 A)
    encoder_k<<<NN, 256>>>(x, encW, encb);

    // CSR + all-layer fp16 B (edges/weights invariant across layers)
    hist_k<<<(NE + 255) / 256, 256>>>(ei);
    scan_k<<<1, 1024>>>();
    scatter_convB_k<<<SCAT_BLKS + CONVB_BLKS, 256>>>(ei, et, relW, rootW);

    // 8 RGCN layers
    for (int l = 0; l < NL; l++) {
        mma_k<<<dim3(NTM, MT), 256>>>(NN, l);
        gather_k<<<NN, 64>>>(convb + (size_t)l * DD, preluA);
    }

    // graph head
    dim3 gDD(DD / 128, (NN + 127) / 128);
    sgemm_k<128, 128, 16, 8, 8><<<gDD, 256>>>(p_h, gpW1, p_t1, NN, DD, DD, gpb1, 1);
    sgemm_k<128, 128, 16, 8, 8><<<gDD, 256>>>(p_t1, gpW2, p_hnew, NN, DD, DD, gpb2, 0);

    zero_f_k<<<(NG * DD + 255) / 256, 256>>>(p_pool, NG * DD);
    pool_k<<<(NN * 64 + 255) / 256, 256>>>(batch);

    sgemm_k<64, 64, 16, 4, 4><<<dim3(1024 / 64, NG / 64), 256>>>(
        p_pool, fcW1, p_z1, NG, 1024, DD, fcb1, 1);
    sgemm_k<64, 64, 16, 4, 4><<<dim3(512 / 64, NG / 64), 256>>>(
        p_z1, fcW2, p_z2, NG, 512, 1024, fcb2, 1);
    out_k<<<NG, 128>>>(outW, outb, out);
}

// round 11
// speedup vs baseline: 6.8176x; 1.1640x over previous
#include <cuda_runtime.h>
#include <cuda_fp16.h>
#include <cstdint>

#define NN   50000
#define NE   800000
#define NREL 6
#define NL   8
#define DD   256
#define NG   512
#define KA   256          // GEMM K (single-pass fp16)
#define NC   1792         // 7*256 (6 rel + root)
#define BM   128
#define BNT  128
#define BK   32
#define MT   391          // ceil(50000/128)
#define NTM  14           // 1792/128
#define SCAT_BLKS  ((NE + 255) / 256)
#define CONVB_ELEMS ((size_t)NL * NC * KA)
#define CONVB_BLKS ((int)((CONVB_ELEMS + 255) / 256))
#define GP_ELEMS   (2 * 256 * 256)
#define GP_BLKS    (GP_ELEMS / 256)

// ---------------- scratch ----------------
__device__ float   g_h   [(size_t)NN * DD];      //  51 MB fp32 hidden state
__device__ __half  g_xWh [(size_t)NN * NC];      // 179 MB fp16 transformed features
__device__ __half  g_Ah  [(size_t)NN * KA];      //  25.6 MB fp16 A (L2-resident)
__device__ __half  g_t1h [(size_t)NN * DD];      //  25.6 MB head intermediate
__device__ __half  g_gout[(size_t)NN * DD];      //  25.6 MB head output (pre-pool)
__device__ __half  g_B8  [CONVB_ELEMS];          //   7.3 MB fp16 all-layer weights
__device__ __half  g_Bgp [GP_ELEMS];             //  gp_W1 / gp_W2 fp16 (n-major)
__device__ int     g_deg [NN];
__device__ int     g_rowptr[NN + 1];
__device__ int     g_cursor[NN];
__device__ unsigned g_epack[NE];
__device__ float   g_pool[NG * DD];
__device__ float   g_z1  [NG * 1024];
__device__ float   g_z2  [NG * 512];

// ---------------- PTX helpers (baseline ISA only) ----------------
__device__ __forceinline__ uint32_t smem_u32(const void* p) {
    uint32_t a;
    asm("{ .reg .u64 t; cvta.to.shared.u64 t, %1; cvt.u32.u64 %0, t; }" : "=r"(a) : "l"(p));
    return a;
}
__device__ __forceinline__ void cp16(uint32_t s, const void* g) {
    asm volatile("cp.async.cg.shared.global [%0], [%1], 16;" :: "r"(s), "l"(g) : "memory");
}
__device__ __forceinline__ void cp_commit() {
    asm volatile("cp.async.commit_group;" ::: "memory");
}
template <int N>
__device__ __forceinline__ void cp_wait() {
    asm volatile("cp.async.wait_group %0;" :: "n"(N) : "memory");
}
__device__ __forceinline__ void ldsm4(uint32_t a, uint32_t* r) {
    asm volatile("ldmatrix.sync.aligned.m8n8.x4.shared.b16 {%0,%1,%2,%3}, [%4];"
                 : "=r"(r[0]), "=r"(r[1]), "=r"(r[2]), "=r"(r[3]) : "r"(a));
}
__device__ __forceinline__ void mma16816(float* c, const uint32_t* a, const uint32_t* b) {
    asm volatile(
        "mma.sync.aligned.m16n8k16.row.col.f32.f16.f16.f32 "
        "{%0,%1,%2,%3}, {%4,%5,%6,%7}, {%8,%9}, {%0,%1,%2,%3};"
        : "+f"(c[0]), "+f"(c[1]), "+f"(c[2]), "+f"(c[3])
        : "r"(a[0]), "r"(a[1]), "r"(a[2]), "r"(a[3]), "r"(b[0]), "r"(b[1]));
}
__device__ __forceinline__ int SW(int row, int cb) {
    return row * 64 + (cb ^ (((row >> 1) & 3) << 4));
}

// ---------------- encoder (+ zero deg, + layer-0 fp16 A) ----------------
__global__ void encoder_k(const float* __restrict__ x, const float* __restrict__ W,
                          const float* __restrict__ b) {
    int n = blockIdx.x;
    if (threadIdx.x == 0) g_deg[n] = 0;
    __shared__ float xr[13];
    if (threadIdx.x < 13) xr[threadIdx.x] = x[n * 13 + threadIdx.x];
    __syncthreads();
    int d = threadIdx.x;
    float s = b[d];
#pragma unroll
    for (int k = 0; k < 13; k++) s += xr[k] * W[k * DD + d];
    g_h[(size_t)n * DD + d] = s;
    g_Ah[(size_t)n * KA + d] = __float2half(s);
}

// ---------------- CSR + all-layer fp16 B + gp weights ----------------
__global__ void hist_k(const int* __restrict__ ei) {
    int e = blockIdx.x * blockDim.x + threadIdx.x;
    if (e < NE) atomicAdd(&g_deg[ei[NE + e]], 1);
}
__global__ void scan_k() {
    __shared__ int wsum[32];
    __shared__ int s_run;
    int t = threadIdx.x, lane = t & 31, w = t >> 5;
    if (t == 0) s_run = 0;
    __syncthreads();
    for (int base = 0; base < NN; base += 1024) {
        int i = base + t;
        int v = (i < NN) ? g_deg[i] : 0;
        int xv = v;
#pragma unroll
        for (int o = 1; o < 32; o <<= 1) {
            int y = __shfl_up_sync(0xffffffffu, xv, o);
            if (lane >= o) xv += y;
        }
        if (lane == 31) wsum[w] = xv;
        __syncthreads();
        if (w == 0) {
            int z = wsum[lane];
#pragma unroll
            for (int o = 1; o < 32; o <<= 1) {
                int y = __shfl_up_sync(0xffffffffu, z, o);
                if (lane >= o) z += y;
            }
            wsum[lane] = z;
        }
        __syncthreads();
        int incl = xv + (w > 0 ? wsum[w - 1] : 0) + s_run;
        if (i < NN) { g_rowptr[i] = incl - v; g_cursor[i] = incl - v; }
        __syncthreads();
        if (t == 1023) s_run = incl;
        __syncthreads();
    }
    if (t == 0) g_rowptr[NN] = s_run;
}
__global__ void scatter_convB_k(const int* __restrict__ ei, const int* __restrict__ et,
                                const float* __restrict__ relW, const float* __restrict__ rootW,
                                const float* __restrict__ gpW1, const float* __restrict__ gpW2) {
    int b = blockIdx.x;
    if (b < SCAT_BLKS) {
        int e = b * 256 + threadIdx.x;
        if (e >= NE) return;
        int dst = ei[NE + e];
        int pos = atomicAdd(&g_cursor[dst], 1);
        g_epack[pos] = (unsigned)ei[e] | ((unsigned)et[e] << 17);   // src:17 bits, type:3
    } else if (b < SCAT_BLKS + CONVB_BLKS) {
        size_t idx = (size_t)(b - SCAT_BLKS) * 256 + threadIdx.x;
        if (idx >= CONVB_ELEMS) return;
        int l = (int)(idx / ((size_t)NC * KA));
        int r2 = (int)(idx % ((size_t)NC * KA));
        int n = r2 / KA, k = r2 - n * KA;
        float wv;
        if (n < 1536) {
            int r = n >> 8, c = n & 255;
            wv = relW[((((size_t)l * NREL + r) * DD + k) * DD) + c];
        } else {
            wv = rootW[(((size_t)l * DD + k) * DD) + (n - 1536)];
        }
        g_B8[idx] = __float2half(wv);
    } else {
        int idx = (b - SCAT_BLKS - CONVB_BLKS) * 256 + threadIdx.x;
        if (idx >= GP_ELEMS) return;
        int m = idx >> 16;           // 0: gpW1, 1: gpW2
        int r = idx & 65535;
        int n = r >> 8, k = r & 255; // B[n][k] = W[k][n]
        const float* W = m ? gpW2 : gpW1;
        g_Bgp[idx] = __float2half(W[k * 256 + n]);
    }
}

// ---------------- fp16 mma.sync GEMM (3-stage, 1 sync/chunk): g_xWh = Ah @ B8[l]^T -----
__global__ __launch_bounds__(256, 2) void mma_k(int M, int layer) {
    __shared__ __align__(16) unsigned char sA[3][BM * 64];
    __shared__ __align__(16) unsigned char sB[3][BNT * 64];

    int tid = threadIdx.x, lane = tid & 31, wid = tid >> 5;
    int wm = (wid & 3) * 32;
    int wn = (wid >> 2) * 64;
    int bm0 = blockIdx.y * BM, bn0 = blockIdx.x * BNT;

    uint32_t aA[3] = {smem_u32(sA[0]), smem_u32(sA[1]), smem_u32(sA[2])};
    uint32_t aB[3] = {smem_u32(sB[0]), smem_u32(sB[1]), smem_u32(sB[2])};

    float acc[2][8][4];
#pragma unroll
    for (int i = 0; i < 2; i++)
#pragma unroll
        for (int j = 0; j < 8; j++)
#pragma unroll
            for (int q = 0; q < 4; q++) acc[i][j][q] = 0.f;

    const __half* A = g_Ah;
    const __half* B = g_B8 + (size_t)layer * NC * KA;

    auto load_stage = [&](int buf, int kc) {
#pragma unroll
        for (int i = 0; i < 2; i++) {
            int id = tid + i * 256;
            int row = id >> 2, cb = (id & 3) * 16;
            int gr = min(bm0 + row, M - 1);
            cp16(aA[buf] + SW(row, cb), A + (size_t)gr * KA + kc * BK + cb / 2);
        }
#pragma unroll
        for (int i = 0; i < 2; i++) {
            int id = tid + i * 256;
            int row = id >> 2, cb = (id & 3) * 16;
            cp16(aB[buf] + SW(row, cb), B + (size_t)(bn0 + row) * KA + kc * BK + cb / 2);
        }
        cp_commit();
    };

    const int NKC = KA / BK;  // 8
    load_stage(0, 0);
    load_stage(1, 1);

    for (int kc = 0; kc < NKC; kc++) {
        if (kc == NKC - 1) cp_wait<0>(); else cp_wait<1>();
        __syncthreads();   // stage kc ready AND all warps done with buf (kc-1)%3 == (kc+2)%3
        if (kc + 2 < NKC) load_stage((kc + 2) % 3, kc + 2);
        int buf = kc % 3;

#pragma unroll
        for (int kkx = 0; kkx < 2; kkx++) {
            uint32_t areg[2][4];
#pragma unroll
            for (int mt = 0; mt < 2; mt++) {
                int row = wm + mt * 16 + (lane & 15);
                int cb = kkx * 32 + ((lane >> 4) << 4);
                ldsm4(aA[buf] + SW(row, cb), areg[mt]);
            }
            uint32_t breg[8][2];
#pragma unroll
            for (int np = 0; np < 4; np++) {
                int row = wn + np * 16 + ((lane >> 4) << 3) + (lane & 7);
                int cb = kkx * 32 + (((lane >> 3) & 1) << 4);
                uint32_t r4[4];
                ldsm4(aB[buf] + SW(row, cb), r4);
                breg[np * 2 + 0][0] = r4[0]; breg[np * 2 + 0][1] = r4[1];
                breg[np * 2 + 1][0] = r4[2]; breg[np * 2 + 1][1] = r4[3];
            }
#pragma unroll
            for (int mt = 0; mt < 2; mt++)
#pragma unroll
                for (int nt = 0; nt < 8; nt++)
                    mma16816(acc[mt][nt], areg[mt], breg[nt]);
        }
    }

#pragma unroll
    for (int mt = 0; mt < 2; mt++) {
        int r0 = bm0 + wm + mt * 16 + (lane >> 2);
#pragma unroll
        for (int nt = 0; nt < 8; nt++) {
            int cn = bn0 + wn + nt * 8 + (lane & 3) * 2;
            if (r0 < M)
                *(__half2*)(g_xWh + (size_t)r0 * NC + cn) =
                    __floats2half2_rn(acc[mt][nt][0], acc[mt][nt][1]);
            if (r0 + 8 < M)
                *(__half2*)(g_xWh + (size_t)(r0 + 8) * NC + cn) =
                    __floats2half2_rn(acc[mt][nt][2], acc[mt][nt][3]);
        }
    }
}

// ---------------- fp16 head GEMM: dst[M,256] = (A @ Bgp[mat]^T + bias)(relu?) ----------
__global__ __launch_bounds__(256, 2) void mma_head_k(const __half* __restrict__ A, int M,
                                                     const __half* __restrict__ B,
                                                     const float* __restrict__ bias, int relu,
                                                     __half* __restrict__ dst) {
    __shared__ __align__(16) unsigned char sA[3][BM * 64];
    __shared__ __align__(16) unsigned char sB[3][BNT * 64];

    int tid = threadIdx.x, lane = tid & 31, wid = tid >> 5;
    int wm = (wid & 3) * 32;
    int wn = (wid >> 2) * 64;
    int bm0 = blockIdx.y * BM, bn0 = blockIdx.x * BNT;

    uint32_t aA[3] = {smem_u32(sA[0]), smem_u32(sA[1]), smem_u32(sA[2])};
    uint32_t aB[3] = {smem_u32(sB[0]), smem_u32(sB[1]), smem_u32(sB[2])};

    float acc[2][8][4];
#pragma unroll
    for (int i = 0; i < 2; i++)
#pragma unroll
        for (int j = 0; j < 8; j++)
#pragma unroll
            for (int q = 0; q < 4; q++) acc[i][j][q] = 0.f;

    auto load_stage = [&](int buf, int kc) {
#pragma unroll
        for (int i = 0; i < 2; i++) {
            int id = tid + i * 256;
            int row = id >> 2, cb = (id & 3) * 16;
            int gr = min(bm0 + row, M - 1);
            cp16(aA[buf] + SW(row, cb), A + (size_t)gr * KA + kc * BK + cb / 2);
        }
#pragma unroll
        for (int i = 0; i < 2; i++) {
            int id = tid + i * 256;
            int row = id >> 2, cb = (id & 3) * 16;
            cp16(aB[buf] + SW(row, cb), B + (size_t)(bn0 + row) * KA + kc * BK + cb / 2);
        }
        cp_commit();
    };

    const int NKC = KA / BK;  // 8
    load_stage(0, 0);
    load_stage(1, 1);

    for (int kc = 0; kc < NKC; kc++) {
        if (kc == NKC - 1) cp_wait<0>(); else cp_wait<1>();
        __syncthreads();
        if (kc + 2 < NKC) load_stage((kc + 2) % 3, kc + 2);
        int buf = kc % 3;

#pragma unroll
        for (int kkx = 0; kkx < 2; kkx++) {
            uint32_t areg[2][4];
#pragma unroll
            for (int mt = 0; mt < 2; mt++) {
                int row = wm + mt * 16 + (lane & 15);
                int cb = kkx * 32 + ((lane >> 4) << 4);
                ldsm4(aA[buf] + SW(row, cb), areg[mt]);
            }
            uint32_t breg[8][2];
#pragma unroll
            for (int np = 0; np < 4; np++) {
                int row = wn + np * 16 + ((lane >> 4) << 3) + (lane & 7);
                int cb = kkx * 32 + (((lane >> 3) & 1) << 4);
                uint32_t r4[4];
                ldsm4(aB[buf] + SW(row, cb), r4);
                breg[np * 2 + 0][0] = r4[0]; breg[np * 2 + 0][1] = r4[1];
                breg[np * 2 + 1][0] = r4[2]; breg[np * 2 + 1][1] = r4[3];
            }
#pragma unroll
            for (int mt = 0; mt < 2; mt++)
#pragma unroll
                for (int nt = 0; nt < 8; nt++)
                    mma16816(acc[mt][nt], areg[mt], breg[nt]);
        }
    }

#pragma unroll
    for (int mt = 0; mt < 2; mt++) {
        int r0 = bm0 + wm + mt * 16 + (lane >> 2);
#pragma unroll
        for (int nt = 0; nt < 8; nt++) {
            int cn = bn0 + wn + nt * 8 + (lane & 3) * 2;
            float b0 = bias[cn], b1 = bias[cn + 1];
            float v0 = acc[mt][nt][0] + b0, v1 = acc[mt][nt][1] + b1;
            float v2 = acc[mt][nt][2] + b0, v3 = acc[mt][nt][3] + b1;
            if (relu) {
                v0 = fmaxf(v0, 0.f); v1 = fmaxf(v1, 0.f);
                v2 = fmaxf(v2, 0.f); v3 = fmaxf(v3, 0.f);
            }
            if (r0 < M)
                *(__half2*)(dst + (size_t)r0 * DD + cn) = __floats2half2_rn(v0, v1);
            if (r0 + 8 < M)
                *(__half2*)(dst + (size_t)(r0 + 8) * DD + cn) = __floats2half2_rn(v2, v3);
        }
    }
}

// ------- fused gather + root + skip + bias + PReLU + L2 norm + next-layer fp16 A -------
__global__ void gather_k(const float* __restrict__ convb, const float* __restrict__ pa) {
    int row = blockIdx.x;
    int t = threadIdx.x;   // 64 threads, 4 cols each
    const __half* xwr = g_xWh + (size_t)row * NC;
    uint2 rr = *(const uint2*)(xwr + 1536 + t * 4);                    // root
    float2 r0 = __half22float2(*(__half2*)&rr.x);
    float2 r1 = __half22float2(*(__half2*)&rr.y);
    float4 acc = make_float4(r0.x, r0.y, r1.x, r1.y);
    float4 h0  = *(const float4*)(g_h + (size_t)row * DD + t * 4);     // skip
    float4 cb  = *(const float4*)(convb + t * 4);
    acc.x += h0.x + cb.x; acc.y += h0.y + cb.y; acc.z += h0.z + cb.z; acc.w += h0.w + cb.w;
    int beg = g_rowptr[row], end = g_rowptr[row + 1];
    for (int i = beg; i < end; i++) {
        unsigned p = g_epack[i];
        int src = p & 0x1FFFF, typ = (p >> 17) & 7;
        uint2 mm = *(const uint2*)(g_xWh + (size_t)src * NC + typ * DD + t * 4);
        float2 m0 = __half22float2(*(__half2*)&mm.x);
        float2 m1 = __half22float2(*(__half2*)&mm.y);
        acc.x += m0.x; acc.y += m0.y; acc.z += m1.x; acc.w += m1.y;
    }
    float a = *pa;
    acc.x = acc.x > 0.f ? acc.x : a * acc.x;
    acc.y = acc.y > 0.f ? acc.y : a * acc.y;
    acc.z = acc.z > 0.f ? acc.z : a * acc.z;
    acc.w = acc.w > 0.f ? acc.w : a * acc.w;
    float s = acc.x * acc.x + acc.y * acc.y + acc.z * acc.z + acc.w * acc.w;
#pragma unroll
    for (int o = 16; o > 0; o >>= 1) s += __shfl_down_sync(0xffffffffu, s, o);
    __shared__ float sm[2];
    if ((t & 31) == 0) sm[t >> 5] = s;
    __syncthreads();
    float inv = 1.f / fmaxf(sqrtf(sm[0] + sm[1]), 1e-12f);
    acc.x *= inv; acc.y *= inv; acc.z *= inv; acc.w *= inv;
    *(float4*)(g_h + (size_t)row * DD + t * 4) = acc;
    __half* arow = g_Ah + (size_t)row * KA + t * 4;
    *(__half2*)(arow)     = __floats2half2_rn(acc.x, acc.y);
    *(__half2*)(arow + 2) = __floats2half2_rn(acc.z, acc.w);
}

// ---------------- fp32 SGEMM (fc head, small) ----------------
template <int BM_, int BN_, int BK_, int TM_, int TN_>
__global__ __launch_bounds__((BM_ / TM_) * (BN_ / TN_))
void sgemm_k(const float* __restrict__ A, const float* __restrict__ B,
             float* __restrict__ C, int M, int N, int K,
             const float* __restrict__ bias, int relu) {
    constexpr int NT = (BM_ / TM_) * (BN_ / TN_);
    __shared__ float As[BK_ * BM_];
    __shared__ float Bs[BK_ * BN_];
    int tid = threadIdx.x;
    int bm0 = blockIdx.y * BM_, bn0 = blockIdx.x * BN_;
    int tr = tid / (BN_ / TN_), tc = tid % (BN_ / TN_);
    float acc[TM_][TN_];
#pragma unroll
    for (int i = 0; i < TM_; i++)
#pragma unroll
        for (int j = 0; j < TN_; j++) acc[i][j] = 0.f;
    constexpr int AIT = (BM_ * BK_ / 4) / NT;
    constexpr int BIT = (BK_ * BN_ / 4) / NT;
    for (int k0 = 0; k0 < K; k0 += BK_) {
#pragma unroll
        for (int it = 0; it < AIT; it++) {
            int i = tid + it * NT;
            int ar = i / (BK_ / 4), ac = (i % (BK_ / 4)) * 4;
            float4 v = make_float4(0.f, 0.f, 0.f, 0.f);
            int gr = bm0 + ar;
            if (gr < M) v = *(const float4*)(A + (size_t)gr * K + k0 + ac);
            As[(ac + 0) * BM_ + ar] = v.x; As[(ac + 1) * BM_ + ar] = v.y;
            As[(ac + 2) * BM_ + ar] = v.z; As[(ac + 3) * BM_ + ar] = v.w;
        }
#pragma unroll
        for (int it = 0; it < BIT; it++) {
            int i = tid + it * NT;
            int br = i / (BN_ / 4), bc = (i % (BN_ / 4)) * 4;
            *(float4*)(Bs + br * BN_ + bc) = *(const float4*)(B + (size_t)(k0 + br) * N + bn0 + bc);
        }
        __syncthreads();
#pragma unroll
        for (int k = 0; k < BK_; k++) {
            float ra[TM_], rb[TN_];
#pragma unroll
            for (int i = 0; i < TM_; i++) ra[i] = As[k * BM_ + tr * TM_ + i];
#pragma unroll
            for (int j = 0; j < TN_; j++) rb[j] = Bs[k * BN_ + tc * TN_ + j];
#pragma unroll
            for (int i = 0; i < TM_; i++)
#pragma unroll
                for (int j = 0; j < TN_; j++) acc[i][j] += ra[i] * rb[j];
        }
        __syncthreads();
    }
#pragma unroll
    for (int i = 0; i < TM_; i++) {
        int row = bm0 + tr * TM_ + i;
        if (row >= M) continue;
#pragma unroll
        for (int j = 0; j < TN_; j += 4) {
            int col = bn0 + tc * TN_ + j;
            float4 v = make_float4(acc[i][j], acc[i][j + 1], acc[i][j + 2], acc[i][j + 3]);
            if (bias) {
                float4 bb = *(const float4*)(bias + col);
                v.x += bb.x; v.y += bb.y; v.z += bb.z; v.w += bb.w;
            }
            if (relu) {
                v.x = fmaxf(v.x, 0.f); v.y = fmaxf(v.y, 0.f);
                v.z = fmaxf(v.z, 0.f); v.w = fmaxf(v.w, 0.f);
            }
            *(float4*)(C + (size_t)row * N + col) = v;
        }
    }
}

// ---------------- pooling + output head ----------------
__global__ void zero_f_k(float* p, int n) {
    int i = blockIdx.x * blockDim.x + threadIdx.x;
    if (i < n) p[i] = 0.f;
}
__global__ void pool_k(const int* __restrict__ batch) {
    int idx = blockIdx.x * blockDim.x + threadIdx.x;
    if (idx >= NN * 64) return;
    int n = idx >> 6, c = idx & 63;
    int bg = batch[n];
    uint2 vv = *(const uint2*)(g_gout + (size_t)n * DD + c * 4);
    float2 v0 = __half22float2(*(__half2*)&vv.x);
    float2 v1 = __half22float2(*(__half2*)&vv.y);
    float* d = g_pool + (size_t)bg * DD + c * 4;
    atomicAdd(d + 0, v0.x); atomicAdd(d + 1, v0.y);
    atomicAdd(d + 2, v1.x); atomicAdd(d + 3, v1.y);
}
__global__ void out_k(const float* __restrict__ W, const float* __restrict__ b,
                      float* __restrict__ out) {
    int g = blockIdx.x;
    int t = threadIdx.x;
    float4 z = *(const float4*)(g_z2 + (size_t)g * 512 + t * 4);
    float4 w = *(const float4*)(W + t * 4);
    float s = z.x * w.x + z.y * w.y + z.z * w.z + z.w * w.w;
#pragma unroll
    for (int o = 16; o > 0; o >>= 1) s += __shfl_down_sync(0xffffffffu, s, o);
    __shared__ float sm[4];
    if ((t & 31) == 0) sm[t >> 5] = s;
    __syncthreads();
    if (t == 0) out[g] = fmaxf(sm[0] + sm[1] + sm[2] + sm[3] + b[0], 0.f);
}

// ---------------- launch ----------------
extern "C" void kernel_launch(void* const* d_in, const int* in_sizes, int n_in,
                              void* d_out, int out_size) {
    const float* x      = (const float*)d_in[0];
    const int*   ei     = (const int*)d_in[1];
    const int*   et     = (const int*)d_in[2];
    const int*   batch  = (const int*)d_in[3];
    const float* encW   = (const float*)d_in[4];
    const float* encb   = (const float*)d_in[5];
    const float* preluA = (const float*)d_in[6];
    const float* relW   = (const float*)d_in[7];
    const float* rootW  = (const float*)d_in[8];
    const float* convb  = (const float*)d_in[9];
    const float* gpW1   = (const float*)d_in[10];
    const float* gpb1   = (const float*)d_in[11];
    const float* gpW2   = (const float*)d_in[12];
    const float* gpb2   = (const float*)d_in[13];
    const float* fcW1   = (const float*)d_in[14];
    const float* fcb1   = (const float*)d_in[15];
    const float* fcW2   = (const float*)d_in[16];
    const float* fcb2   = (const float*)d_in[17];
    const float* outW   = (const float*)d_in[18];
    const float* outb   = (const float*)d_in[19];
    float*       out    = (float*)d_out;

    float *p_pool, *p_z1, *p_z2;
    __half *p_Ah, *p_t1h, *p_gout, *p_Bgp;
    cudaGetSymbolAddress((void**)&p_pool, g_pool);
    cudaGetSymbolAddress((void**)&p_z1, g_z1);
    cudaGetSymbolAddress((void**)&p_z2, g_z2);
    cudaGetSymbolAddress((void**)&p_Ah, g_Ah);
    cudaGetSymbolAddress((void**)&p_t1h, g_t1h);
    cudaGetSymbolAddress((void**)&p_gout, g_gout);
    cudaGetSymbolAddress((void**)&p_Bgp, g_Bgp);

    // encoder (+ deg zero + layer-0 fp16 A)
    encoder_k<<<NN, 256>>>(x, encW, encb);

    // CSR + all-layer fp16 B + gp weight conversion
    hist_k<<<(NE + 255) / 256, 256>>>(ei);
    scan_k<<<1, 1024>>>();
    scatter_convB_k<<<SCAT_BLKS + CONVB_BLKS + GP_BLKS, 256>>>(ei, et, relW, rootW, gpW1, gpW2);

    // 8 RGCN layers
    for (int l = 0; l < NL; l++) {
        mma_k<<<dim3(NTM, MT), 256>>>(NN, l);
        gather_k<<<NN, 64>>>(convb + (size_t)l * DD, preluA);
    }

    // graph head (fp16 tensor path)
    mma_head_k<<<dim3(2, MT), 256>>>(p_Ah, NN, p_Bgp, gpb1, 1, p_t1h);
    mma_head_k<<<dim3(2, MT), 256>>>(p_t1h, NN, p_Bgp + 65536, gpb2, 0, p_gout);

    zero_f_k<<<(NG * DD + 255) / 256, 256>>>(p_pool, NG * DD);
    pool_k<<<(NN * 64 + 255) / 256, 256>>>(batch);

    sgemm_k<64, 64, 16, 4, 4><<<dim3(1024 / 64, NG / 64), 256>>>(
        p_pool, fcW1, p_z1, NG, 1024, DD, fcb1, 1);
    sgemm_k<64, 64, 16, 4, 4><<<dim3(512 / 64, NG / 64), 256>>>(
        p_z1, fcW2, p_z2, NG, 512, 1024, fcb2, 1);
    out_k<<<NG, 128>>>(outW, outb, out);
}